// round 9
// baseline (speedup 1.0000x reference)
#include <cuda_runtime.h>
#include <cuda_bf16.h>
#include <cstdint>

#define N_NODES 32
#define D_EMB   96
#define P_PAIRS 1024
#define M_TOT   262144   // P_PAIRS * 256

// ---- scratch (device globals: no allocations allowed) ----
__device__ float g_G[16 * M_TOT];       // conv features [feature][sample]
__device__ float g_preds[M_TOT];
__device__ float g_part[P_PAIRS * 32];
// weight images: bf16 hi/lo, pre-transposed [n][k], pre-swizzled (W2/W3)
__device__ __align__(16) __nv_bfloat16 g_W1[6144];    // [n=128][kp=24] hi | lo
__device__ __align__(16) __nv_bfloat16 g_W2[131072];  // 8 pieces of 8192: (h,c)->hi,lo
__device__ __align__(16) __nv_bfloat16 g_W3[65536];   // 4 pieces of 16384: (kh)->hi,lo

// ---------------- helpers ----------------
__device__ __forceinline__ uint32_t smem_u32(const void* p) {
    uint32_t a;
    asm("{ .reg .u64 t; cvta.to.shared.u64 t, %1; cvt.u32.u64 %0, t; }" : "=r"(a) : "l"(p));
    return a;
}
__device__ __forceinline__ uint32_t swz(int m, int kb, int rowb) {
    return (uint32_t)(m * rowb + (kb ^ ((m & 7) << 4)));
}
__device__ __forceinline__ void ldsm4(uint32_t a, uint32_t* r) {
    asm volatile("ldmatrix.sync.aligned.m8n8.x4.shared.b16 {%0,%1,%2,%3}, [%4];"
        : "=r"(r[0]), "=r"(r[1]), "=r"(r[2]), "=r"(r[3]) : "r"(a));
}
__device__ __forceinline__ void mma16816(float* c, const uint32_t* a, uint32_t b0, uint32_t b1) {
    asm volatile("mma.sync.aligned.m16n8k16.row.col.f32.bf16.bf16.f32 "
        "{%0,%1,%2,%3}, {%4,%5,%6,%7}, {%8,%9}, {%0,%1,%2,%3};"
        : "+f"(c[0]), "+f"(c[1]), "+f"(c[2]), "+f"(c[3])
        : "r"(a[0]), "r"(a[1]), "r"(a[2]), "r"(a[3]), "r"(b0), "r"(b1));
}
__device__ __forceinline__ void bsplit(float x, __nv_bfloat16& h, __nv_bfloat16& l) {
    h = __float2bfloat16_rn(x);
    l = __float2bfloat16_rn(x - __bfloat162float(h));
}
__device__ __forceinline__ uint32_t pk(__nv_bfloat16 lo, __nv_bfloat16 hi) {
    return (uint32_t)__bfloat16_as_ushort(hi) << 16 | (uint32_t)__bfloat16_as_ushort(lo);
}
__device__ __forceinline__ void sts32(uint32_t addr, uint32_t v) {
    asm volatile("st.shared.b32 [%0], %1;" :: "r"(addr), "r"(v) : "memory");
}
__device__ __forceinline__ void copyg(void* dst, const __nv_bfloat16* src, int bytes, int tid) {
    float4* d = (float4*)dst; const float4* s = (const float4*)src;
    for (int i = tid; i < (bytes >> 4); i += 256) d[i] = s[i];
}
// ---- cp.async (LDGSTS) ----
__device__ __forceinline__ void cpa16(uint32_t saddr, const void* g) {
    asm volatile("cp.async.cg.shared.global [%0], [%1], 16;" :: "r"(saddr), "l"(g) : "memory");
}
#define CP_COMMIT() asm volatile("cp.async.commit_group;" ::: "memory")
#define CP_WAIT0()  asm volatile("cp.async.wait_group 0;" ::: "memory")
__device__ __forceinline__ void stage16k(uint32_t sbuf, const __nv_bfloat16* src, int tid) {
    #pragma unroll
    for (int i = 0; i < 4; i++) {
        int idx = tid + i * 256;
        cpa16(sbuf + idx * 16, (const char*)src + idx * 16);
    }
}
__device__ __forceinline__ void stage32k(uint32_t sbuf, const __nv_bfloat16* src, int tid) {
    #pragma unroll
    for (int i = 0; i < 8; i++) {
        int idx = tid + i * 256;
        cpa16(sbuf + idx * 16, (const char*)src + idx * 16);
    }
}

// =====================================================================
// Kernel 0: prep — split weights to bf16 hi/lo images
// =====================================================================
__global__ void __launch_bounds__(256) prep_kernel(
    const float* __restrict__ fc1w, const float* __restrict__ fc2w,
    const float* __restrict__ fc3w)
{
    int idx = blockIdx.x * 256 + threadIdx.x;   // 0 .. 68607
    if (idx < 3072) {                 // W1: [n=128][kp=24], linear (padded)
        int n = idx / 24, k = idx % 24;
        float val = (k < 16) ? fc1w[k * 128 + n] : 0.0f;
        __nv_bfloat16 hh, ll; bsplit(val, hh, ll);
        g_W1[n * 24 + k] = hh; g_W1[3072 + n * 24 + k] = ll;
    } else if (idx < 35840) {         // W2: pieces [(h*2+c)]: hi 8192 | lo 8192, rowb=128
        int j = idx - 3072;
        int h = j >> 14, c = (j >> 13) & 1;
        int j2 = j & 8191;
        int n = j2 >> 6, k = j2 & 63;
        float val = fc2w[(c * 64 + k) * 256 + h * 128 + n];
        int eo = n * 64 + (((k * 2) ^ ((n & 7) << 4)) >> 1);
        int ph = (h * 2 + c) * 16384 + eo;
        __nv_bfloat16 hh, ll; bsplit(val, hh, ll);
        g_W2[ph] = hh; g_W2[ph + 8192] = ll;
    } else {                          // W3: k-halves, [128n][128k] rowb=256 swizzle
        int j = idx - 35840;          // 0..32767
        int n = j >> 8, k = j & 255;
        int kh = k >> 7, kl = k & 127;
        float val = fc3w[k * 128 + n];
        int eo = n * 128 + (((kl * 2) ^ ((n & 7) << 4)) >> 1);
        int ph = kh * 32768 + eo;
        __nv_bfloat16 hh, ll; bsplit(val, hh, ll);
        g_W3[ph] = hh; g_W3[ph + 16384] = ll;
    }
}

// =====================================================================
// Kernel 1: conv stack, conv1 decomposed into per-node linear parts.
// R[c*32+n][o*47+i] = sum_k w1[o][c][k] * emb[n][2i+k]   (row pad 191)
// Then conv1[m][o][i] = R0[s]+R1[t]+R2[u]+R3[v]+b1 (3 adds), relu+pool.
// Dynamic smem: semb 32*96 | R 128*191.  Skips s==t blocks.
// =====================================================================
#define RP 191
#define CONV_SMEM ((N_NODES * D_EMB + 128 * RP) * 4)

__global__ void __launch_bounds__(256) conv_kernel(
    const float* __restrict__ emb, const int* __restrict__ edges,
    const float* __restrict__ w1, const float* __restrict__ b1,
    const float* __restrict__ w2, const float* __restrict__ b2,
    const float* __restrict__ w3, const float* __restrict__ b3)
{
    int p = blockIdx.x;
    int s = p >> 5, t = p & 31;
    if (s == t) return;               // fc skips these tiles; output unused

    extern __shared__ float dsm[];
    float* semb = dsm;                    // 3072
    float* R    = dsm + N_NODES * D_EMB;  // 128*191
    __shared__ float sw1[48], sw2[48], sw3[48];
    __shared__ float sb1[4], sb2[4], sb3[4];
    int tid = threadIdx.x;
    for (int i = tid; i < N_NODES * D_EMB; i += 256) semb[i] = emb[i];
    if (tid < 48) { sw1[tid] = w1[tid]; sw2[tid] = w2[tid]; sw3[tid] = w3[tid]; }
    if (tid < 4)  { sb1[tid] = b1[tid]; sb2[tid] = b2[tid]; sb3[tid] = b3[tid]; }
    __syncthreads();

    // build R: 128 rows x 188 cols, 3 MACs each
    for (int idx = tid; idx < 128 * 188; idx += 256) {
        int row = idx / 188;          // c*32 + n
        int oi  = idx - row * 188;    // o*47 + i
        int c = row >> 5, n = row & 31;
        int o = oi / 47, i = oi - o * 47;
        const float* x = semb + n * D_EMB + 2 * i;
        const float* wv = sw1 + (o * 4 + c) * 3;
        R[row * RP + oi] = wv[0] * x[0] + wv[1] * x[1] + wv[2] * x[2];
    }
    __syncthreads();

    int m = p * 256 + tid;
    int e = tid;
    int u = edges[2 * e], v = edges[2 * e + 1];
    const float* R0 = R + s * RP;
    const float* R1 = R + (32 + t) * RP;
    const float* R2 = R + (64 + u) * RP;
    const float* R3 = R + (96 + v) * RP;

    // conv1 (decomposed) + relu + pool -> p1[4][23]
    float p1[4][23];
    #pragma unroll
    for (int o = 0; o < 4; o++) {
        float bo = sb1[o];
        #pragma unroll
        for (int i = 0; i < 23; i++) {
            int oi = o * 47 + 2 * i;
            float r0 = R0[oi]     + R1[oi]     + R2[oi]     + R3[oi]     + bo;
            float r1 = R0[oi + 1] + R1[oi + 1] + R2[oi + 1] + R3[oi + 1] + bo;
            p1[o][i] = fmaxf(fmaxf(r0, r1), 0.0f);
        }
    }

    // conv2 (stride 1, 23->21) + relu + pool2 -> 10
    float p2[4][10];
    #pragma unroll
    for (int i = 0; i < 10; i++) {
        #pragma unroll
        for (int o = 0; o < 4; o++) {
            float a0 = sb2[o], a1 = sb2[o];
            #pragma unroll
            for (int c = 0; c < 4; c++)
                #pragma unroll
                for (int k = 0; k < 3; k++) {
                    float wv = sw2[(o * 4 + c) * 3 + k];
                    a0 = fmaf(wv, p1[c][2 * i + k],     a0);
                    a1 = fmaf(wv, p1[c][2 * i + 1 + k], a1);
                }
            p2[o][i] = fmaxf(fmaxf(a0, a1), 0.0f);
        }
    }
    // conv3 (10->8) + relu + pool2 -> 4; flatten [o*4 + pos]
    #pragma unroll
    for (int pos = 0; pos < 4; pos++) {
        #pragma unroll
        for (int o = 0; o < 4; o++) {
            float a0 = sb3[o], a1 = sb3[o];
            #pragma unroll
            for (int c = 0; c < 4; c++)
                #pragma unroll
                for (int k = 0; k < 3; k++) {
                    float wv = sw3[(o * 4 + c) * 3 + k];
                    a0 = fmaf(wv, p2[c][2 * pos + k],     a0);
                    a1 = fmaf(wv, p2[c][2 * pos + 1 + k], a1);
                }
            g_G[(o * 4 + pos) * M_TOT + m] = fmaxf(fmaxf(a0, a1), 0.0f);
        }
    }
}

// =====================================================================
// Kernel 2: fused FC chain on HMMA, cp.async double-buffered staging.
// =====================================================================
#define OFF_A2  0
#define OFF_A3  65536
#define OFF_WST 196608
#define FC_SMEM 229376

__device__ __forceinline__ void zero_acc(float acc[2][8][4]) {
    #pragma unroll
    for (int i = 0; i < 2; i++)
        #pragma unroll
        for (int j = 0; j < 8; j++)
            #pragma unroll
            for (int q = 0; q < 4; q++) acc[i][j][q] = 0.f;
}
__device__ __forceinline__ void mma_tile(float acc[2][8][4],
                                         uint32_t a[2][4], uint32_t b[4][4]) {
    #pragma unroll
    for (int i = 0; i < 2; i++)
        #pragma unroll
        for (int p = 0; p < 4; p++) {
            mma16816(acc[i][2 * p],     a[i], b[p][0], b[p][1]);
            mma16816(acc[i][2 * p + 1], a[i], b[p][2], b[p][3]);
        }
}
__device__ __forceinline__ void load_afrag(uint32_t base, int mb, int kb0, int rowb,
                                           int mi, int r8, uint32_t a[2][4]) {
    #pragma unroll
    for (int i = 0; i < 2; i++) {
        int m = mb + i * 16 + r8 + ((mi & 1) << 3);
        int kb = kb0 + ((mi >> 1) << 4);
        ldsm4(base + swz(m, kb, rowb), a[i]);
    }
}
__device__ __forceinline__ void load_bfrag(uint32_t base, int nb, int kb0, int rowb,
                                           int mi, int r8, uint32_t b[4][4]) {
    #pragma unroll
    for (int p = 0; p < 4; p++) {
        int n = nb + p * 16 + r8 + ((mi >> 1) << 3);
        int kb = kb0 + ((mi & 1) << 4);
        ldsm4(base + swz(n, kb, rowb), b[p]);
    }
}
__device__ __forceinline__ void store_pair(uint32_t hib, uint32_t lob, int m, int col,
                                           int rowb, float v0, float v1) {
    __nv_bfloat16 h0, l0, h1, l1;
    bsplit(v0, h0, l0); bsplit(v1, h1, l1);
    uint32_t off = swz(m, col * 2, rowb);
    sts32(hib + off, pk(h0, h1));
    sts32(lob + off, pk(l0, l1));
}
__device__ __forceinline__ void epilogue_act(float acc[2][8][4],
    uint32_t hib, uint32_t lob, int rowb, int mb, int nb, int kofs,
    const float* __restrict__ bias, int r4, int c4)
{
    #pragma unroll
    for (int i = 0; i < 2; i++)
        #pragma unroll
        for (int j = 0; j < 8; j++) {
            int col = nb + j * 8 + c4 * 2;
            int dc = kofs + col;
            float b0 = __ldg(bias + dc), b1 = __ldg(bias + dc + 1);
            int m = mb + i * 16 + r4;
            store_pair(hib, lob, m, dc, rowb,
                       fmaxf(acc[i][j][0] + b0, 0.f), fmaxf(acc[i][j][1] + b1, 0.f));
            store_pair(hib, lob, m + 8, dc, rowb,
                       fmaxf(acc[i][j][2] + b0, 0.f), fmaxf(acc[i][j][3] + b1, 0.f));
        }
}

__global__ void __launch_bounds__(256) fc_kernel(
    const float* __restrict__ fc1b, const float* __restrict__ fc2b,
    const float* __restrict__ fc3b, const float* __restrict__ fc4w,
    const float* __restrict__ fc4b)
{
    const int m0 = blockIdx.x * 128;
    const int pp = m0 >> 8;
    if ((pp >> 5) == (pp & 31)) return;   // masked tile: prop writes zeros itself

    extern __shared__ char sm[];
    const uint32_t smb = smem_u32(sm);
    const int tid = threadIdx.x;
    const int l = tid & 31, w = tid >> 5;
    const int wm = w & 3, wn = w >> 2;
    const int mb = wm * 32, nb = wn * 64;
    const int mi = l >> 3, r8 = l & 7;
    const int r4 = l >> 2, c4 = l & 3;

    const uint32_t A1h = smb + OFF_A3, A1l = A1h + 6144;
    const uint32_t W1h = A1h + 12288, W1l = A1h + 18432;
    const uint32_t A2h = smb + OFF_A2, A2l = A2h + 32768;
    const uint32_t A3h = smb + OFF_A3, A3l = A3h + 65536;
    const uint32_t WST = smb + OFF_WST;

    // pre-issue fc2 piece 0 into WST buf0 (hidden under fc1 staging/compute)
    stage16k(WST, g_W2, tid); CP_COMMIT();

    // ---- stage A1 (from g_G, padded kp=24) + W1 ----
    {
        __nv_bfloat16* a1h = (__nv_bfloat16*)(sm + OFF_A3);
        __nv_bfloat16* a1l = (__nv_bfloat16*)(sm + OFF_A3 + 6144);
        for (int idx = tid; idx < 2048; idx += 256) {
            int k = idx >> 7, m = idx & 127;
            float v = g_G[k * M_TOT + m0 + m];
            __nv_bfloat16 h, lo; bsplit(v, h, lo);
            a1h[m * 24 + k] = h; a1l[m * 24 + k] = lo;
        }
        copyg(sm + OFF_A3 + 12288, g_W1, 12288, tid);
    }
    __syncthreads();

    float acc[2][8][4];
    uint32_t ah[2][4], al[2][4], bh[4][4], bl[4][4];

    // ---- fc1: K=16, N=128 -> A2 ----
    zero_acc(acc);
    {
        #pragma unroll
        for (int i = 0; i < 2; i++) {
            int m = mb + i * 16 + r8 + ((mi & 1) << 3);
            int kb = (mi >> 1) << 4;
            ldsm4(A1h + m * 48 + kb, ah[i]);
            ldsm4(A1l + m * 48 + kb, al[i]);
        }
        #pragma unroll
        for (int p = 0; p < 4; p++) {
            int n = nb + p * 16 + r8 + ((mi >> 1) << 3);
            int kb = (mi & 1) << 4;
            ldsm4(W1h + n * 48 + kb, bh[p]);
            ldsm4(W1l + n * 48 + kb, bl[p]);
        }
        mma_tile(acc, ah, bh);
        mma_tile(acc, ah, bl);
        mma_tile(acc, al, bh);
    }
    epilogue_act(acc, A2h, A2l, 256, mb, nb, 0, fc1b, r4, c4);

    // ---- fc2: K=128, N=256. 8 pipelined pieces of 16KB: (h,c)->hi,lo ----
    #pragma unroll 1
    for (int ip = 0; ip < 8; ip++) {
        CP_WAIT0();
        __syncthreads();     // piece ip visible; all warps done with piece ip-1
        if (ip < 7) { stage16k(WST + ((ip + 1) & 1) * 16384, g_W2 + (ip + 1) * 8192, tid); CP_COMMIT(); }
        const int h = ip >> 2, c = (ip >> 1) & 1, term = ip & 1;
        if ((ip & 3) == 0) zero_acc(acc);
        const uint32_t wb = WST + (ip & 1) * 16384;
        #pragma unroll
        for (int ks = 0; ks < 4; ks++) {
            int kbA = (c * 64 + ks * 16) * 2;
            int kbW = ks * 32;
            if (term == 0) {
                load_afrag(A2h, mb, kbA, 256, mi, r8, ah);
                load_afrag(A2l, mb, kbA, 256, mi, r8, al);
                load_bfrag(wb, nb, kbW, 128, mi, r8, bh);
                mma_tile(acc, ah, bh);
                mma_tile(acc, al, bh);
            } else {
                load_afrag(A2h, mb, kbA, 256, mi, r8, ah);
                load_bfrag(wb, nb, kbW, 128, mi, r8, bl);
                mma_tile(acc, ah, bl);
            }
        }
        if (ip == 3) epilogue_act(acc, A3h, A3l, 512, mb, nb, 0,   fc2b, r4, c4);
        if (ip == 7) epilogue_act(acc, A3h, A3l, 512, mb, nb, 128, fc2b, r4, c4);
    }
    __syncthreads();   // all warps done reading A2 + fc2 epilogue written

    // ---- fc3: K=256, N=128. 4 pipelined pieces of 32KB in A2 region ----
    stage32k(smb + OFF_A2, g_W3, tid); CP_COMMIT();
    zero_acc(acc);
    #pragma unroll 1
    for (int ip = 0; ip < 4; ip++) {
        CP_WAIT0();
        __syncthreads();
        if (ip < 3) { stage32k(smb + OFF_A2 + ((ip + 1) & 1) * 32768, g_W3 + (ip + 1) * 16384, tid); CP_COMMIT(); }
        const int kh = ip >> 1, term = ip & 1;
        const uint32_t wb = smb + OFF_A2 + (ip & 1) * 32768;
        #pragma unroll
        for (int ks = 0; ks < 8; ks++) {
            int kbA = (kh * 128 + ks * 16) * 2;
            int kbW = ks * 32;
            if (term == 0) {
                load_afrag(A3h, mb, kbA, 512, mi, r8, ah);
                load_afrag(A3l, mb, kbA, 512, mi, r8, al);
                load_bfrag(wb, nb, kbW, 256, mi, r8, bh);
                mma_tile(acc, ah, bh);
                mma_tile(acc, al, bh);
            } else {
                load_afrag(A3h, mb, kbA, 512, mi, r8, ah);
                load_bfrag(wb, nb, kbW, 256, mi, r8, bl);
                mma_tile(acc, ah, bl);
            }
        }
    }

    // ---- fc4: bias+relu+dot in regs, quad-shfl reduce, smem combine ----
    float part[4] = {0.f, 0.f, 0.f, 0.f};
    #pragma unroll
    for (int i = 0; i < 2; i++)
        #pragma unroll
        for (int j = 0; j < 8; j++) {
            int col = nb + j * 8 + c4 * 2;
            float b0 = __ldg(fc3b + col), b1 = __ldg(fc3b + col + 1);
            float w0 = __ldg(fc4w + col), w1 = __ldg(fc4w + col + 1);
            part[i * 2 + 0] += fmaxf(acc[i][j][0] + b0, 0.f) * w0
                             + fmaxf(acc[i][j][1] + b1, 0.f) * w1;
            part[i * 2 + 1] += fmaxf(acc[i][j][2] + b0, 0.f) * w0
                             + fmaxf(acc[i][j][3] + b1, 0.f) * w1;
        }
    #pragma unroll
    for (int q = 0; q < 4; q++) {
        part[q] += __shfl_xor_sync(0xffffffff, part[q], 1);
        part[q] += __shfl_xor_sync(0xffffffff, part[q], 2);
    }
    float* red = (float*)(sm + OFF_WST);
    __syncthreads();
    if (c4 == 0) {
        #pragma unroll
        for (int i = 0; i < 2; i++) {
            red[wn * 128 + mb + i * 16 + r4]     = part[i * 2];
            red[wn * 128 + mb + i * 16 + r4 + 8] = part[i * 2 + 1];
        }
    }
    __syncthreads();
    if (tid < 128) {
        float v = red[tid] + red[128 + tid] + __ldg(fc4b);
        g_preds[m0 + tid] = v;
    }
}

// =====================================================================
// Kernel 3: 3-step propagation, block per p. Deterministic.
// =====================================================================
__global__ void __launch_bounds__(256) prop_kernel(const int* __restrict__ edges)
{
    __shared__ float xs[32];
    __shared__ float xn[8][32];
    __shared__ float acc[32];
    __shared__ float pr[256];
    __shared__ int   su[256], sv[256];
    int tid = threadIdx.x;
    int p = blockIdx.x;
    int s = p >> 5, t = p & 31;
    su[tid] = edges[2 * tid];
    sv[tid] = edges[2 * tid + 1];
    if (s != t) pr[tid] = g_preds[p * 256 + tid];
    if (tid < 32) { xs[tid] = (tid == s) ? 1.0f : 0.0f; acc[tid] = 0.0f; }
    __syncthreads();
    if (s != t) {
        int j = tid & 31, grp = tid >> 5;
        for (int step = 0; step < 3; step++) {
            float sum = 0.0f;
            #pragma unroll 4
            for (int q = 0; q < 32; q++) {
                int e = grp * 32 + q;
                sum += (sv[e] == j) ? xs[su[e]] * pr[e] : 0.0f;
            }
            xn[grp][j] = sum;
            __syncthreads();
            if (tid < 32) {
                float v = 0.0f;
                #pragma unroll
                for (int g2 = 0; g2 < 8; g2++) v += xn[g2][tid];
                xs[tid] = v;
                acc[tid] += v;
            }
            __syncthreads();
        }
    }
    if (tid < 32) g_part[p * 32 + tid] = acc[tid];
}

// =====================================================================
// Kernel 4: final reduction + normalize.
// =====================================================================
__global__ void __launch_bounds__(1024) reduce_kernel(float* __restrict__ out)
{
    __shared__ float red[32][32];
    __shared__ float rbc[32];
    __shared__ float tot;
    int tid = threadIdx.x;
    int j = tid & 31, chunk = tid >> 5;
    float sum = 0.0f;
    for (int q = 0; q < 32; q++)
        sum += g_part[(chunk * 32 + q) * 32 + j];
    red[chunk][j] = sum;
    __syncthreads();
    if (tid < 32) {
        float v = 0.0f;
        for (int c = 0; c < 32; c++) v += red[c][tid];
        rbc[tid] = v;
    }
    __syncthreads();
    if (tid == 0) {
        float tt = 0.0f;
        for (int k = 0; k < 32; k++) tt += rbc[k];
        tot = tt;
    }
    __syncthreads();
    if (tid < 32) out[tid] = rbc[tid] / tot;
}

// =====================================================================
extern "C" void kernel_launch(void* const* d_in, const int* in_sizes, int n_in,
                              void* d_out, int out_size)
{
    const float* emb   = (const float*)d_in[0];
    const int*   edges = (const int*)  d_in[1];
    const float* w1    = (const float*)d_in[2];
    const float* b1    = (const float*)d_in[3];
    const float* w2    = (const float*)d_in[4];
    const float* b2    = (const float*)d_in[5];
    const float* w3    = (const float*)d_in[6];
    const float* b3    = (const float*)d_in[7];
    const float* fc1w  = (const float*)d_in[8];
    const float* fc1b  = (const float*)d_in[9];
    const float* fc2w  = (const float*)d_in[10];
    const float* fc2b  = (const float*)d_in[11];
    const float* fc3w  = (const float*)d_in[12];
    const float* fc3b  = (const float*)d_in[13];
    const float* fc4w  = (const float*)d_in[14];
    const float* fc4b  = (const float*)d_in[15];

    prep_kernel<<<268, 256>>>(fc1w, fc2w, fc3w);

    cudaFuncSetAttribute(conv_kernel, cudaFuncAttributeMaxDynamicSharedMemorySize, CONV_SMEM);
    conv_kernel<<<P_PAIRS, 256, CONV_SMEM>>>(emb, edges, w1, b1, w2, b2, w3, b3);

    cudaFuncSetAttribute(fc_kernel, cudaFuncAttributeMaxDynamicSharedMemorySize, FC_SMEM);
    fc_kernel<<<M_TOT / 128, 256, FC_SMEM>>>(fc1b, fc2b, fc3b, fc4w, fc4b);

    prop_kernel<<<P_PAIRS, 256>>>(edges);
    reduce_kernel<<<1, 1024>>>((float*)d_out);
}

// round 11
// speedup vs baseline: 1.0460x; 1.0460x over previous
#include <cuda_runtime.h>
#include <cuda_bf16.h>
#include <cstdint>

#define N_NODES 32
#define D_EMB   96
#define P_PAIRS 1024
#define M_TOT   262144   // P_PAIRS * 256

// ---- scratch (device globals: no allocations allowed) ----
__device__ float g_G[16 * M_TOT];       // conv features [feature][sample]
__device__ float g_preds[M_TOT];
__device__ float g_part[P_PAIRS * 32];
// weight images: bf16 hi/lo, pre-transposed [n][k], pre-swizzled (W2/W3)
__device__ __align__(16) __nv_bfloat16 g_W1[6144];    // [n=128][kp=24] hi | lo
__device__ __align__(16) __nv_bfloat16 g_W2[131072];  // 8 pieces of 8192: (h,c)->hi,lo
__device__ __align__(16) __nv_bfloat16 g_W3[65536];   // 4 pieces of 16384: (kh)->hi,lo

// ---------------- helpers ----------------
__device__ __forceinline__ uint32_t smem_u32(const void* p) {
    uint32_t a;
    asm("{ .reg .u64 t; cvta.to.shared.u64 t, %1; cvt.u32.u64 %0, t; }" : "=r"(a) : "l"(p));
    return a;
}
__device__ __forceinline__ uint32_t swz(int m, int kb, int rowb) {
    return (uint32_t)(m * rowb + (kb ^ ((m & 7) << 4)));
}
__device__ __forceinline__ void ldsm4(uint32_t a, uint32_t* r) {
    asm volatile("ldmatrix.sync.aligned.m8n8.x4.shared.b16 {%0,%1,%2,%3}, [%4];"
        : "=r"(r[0]), "=r"(r[1]), "=r"(r[2]), "=r"(r[3]) : "r"(a));
}
__device__ __forceinline__ void mma16816(float* c, const uint32_t* a, uint32_t b0, uint32_t b1) {
    asm volatile("mma.sync.aligned.m16n8k16.row.col.f32.bf16.bf16.f32 "
        "{%0,%1,%2,%3}, {%4,%5,%6,%7}, {%8,%9}, {%0,%1,%2,%3};"
        : "+f"(c[0]), "+f"(c[1]), "+f"(c[2]), "+f"(c[3])
        : "r"(a[0]), "r"(a[1]), "r"(a[2]), "r"(a[3]), "r"(b0), "r"(b1));
}
__device__ __forceinline__ void bsplit(float x, __nv_bfloat16& h, __nv_bfloat16& l) {
    h = __float2bfloat16_rn(x);
    l = __float2bfloat16_rn(x - __bfloat162float(h));
}
__device__ __forceinline__ uint32_t pk(__nv_bfloat16 lo, __nv_bfloat16 hi) {
    return (uint32_t)__bfloat16_as_ushort(hi) << 16 | (uint32_t)__bfloat16_as_ushort(lo);
}
__device__ __forceinline__ void sts32(uint32_t addr, uint32_t v) {
    asm volatile("st.shared.b32 [%0], %1;" :: "r"(addr), "r"(v) : "memory");
}
__device__ __forceinline__ void copyg(void* dst, const __nv_bfloat16* src, int bytes, int tid) {
    float4* d = (float4*)dst; const float4* s = (const float4*)src;
    for (int i = tid; i < (bytes >> 4); i += 256) d[i] = s[i];
}
// ---- cp.async (LDGSTS) ----
__device__ __forceinline__ void cpa16(uint32_t saddr, const void* g) {
    asm volatile("cp.async.cg.shared.global [%0], [%1], 16;" :: "r"(saddr), "l"(g) : "memory");
}
#define CP_COMMIT() asm volatile("cp.async.commit_group;" ::: "memory")
#define CP_WAIT0()  asm volatile("cp.async.wait_group 0;" ::: "memory")
__device__ __forceinline__ void stage16k(uint32_t sbuf, const __nv_bfloat16* src, int tid) {
    #pragma unroll
    for (int i = 0; i < 4; i++) {
        int idx = tid + i * 256;
        cpa16(sbuf + idx * 16, (const char*)src + idx * 16);
    }
}
__device__ __forceinline__ void stage32k(uint32_t sbuf, const __nv_bfloat16* src, int tid) {
    #pragma unroll
    for (int i = 0; i < 8; i++) {
        int idx = tid + i * 256;
        cpa16(sbuf + idx * 16, (const char*)src + idx * 16);
    }
}

// =====================================================================
// Kernel 0: prep — split weights to bf16 hi/lo images
// =====================================================================
__global__ void __launch_bounds__(256) prep_kernel(
    const float* __restrict__ fc1w, const float* __restrict__ fc2w,
    const float* __restrict__ fc3w)
{
    int idx = blockIdx.x * 256 + threadIdx.x;   // 0 .. 68607
    if (idx < 3072) {                 // W1: [n=128][kp=24], linear (padded)
        int n = idx / 24, k = idx % 24;
        float val = (k < 16) ? fc1w[k * 128 + n] : 0.0f;
        __nv_bfloat16 hh, ll; bsplit(val, hh, ll);
        g_W1[n * 24 + k] = hh; g_W1[3072 + n * 24 + k] = ll;
    } else if (idx < 35840) {         // W2: pieces [(h*2+c)]: hi 8192 | lo 8192, rowb=128
        int j = idx - 3072;
        int h = j >> 14, c = (j >> 13) & 1;
        int j2 = j & 8191;
        int n = j2 >> 6, k = j2 & 63;
        float val = fc2w[(c * 64 + k) * 256 + h * 128 + n];
        int eo = n * 64 + (((k * 2) ^ ((n & 7) << 4)) >> 1);
        int ph = (h * 2 + c) * 16384 + eo;
        __nv_bfloat16 hh, ll; bsplit(val, hh, ll);
        g_W2[ph] = hh; g_W2[ph + 8192] = ll;
    } else {                          // W3: k-halves, [128n][128k] rowb=256 swizzle
        int j = idx - 35840;          // 0..32767
        int n = j >> 8, k = j & 255;
        int kh = k >> 7, kl = k & 127;
        float val = fc3w[k * 128 + n];
        int eo = n * 128 + (((kl * 2) ^ ((n & 7) << 4)) >> 1);
        int ph = kh * 32768 + eo;
        __nv_bfloat16 hh, ll; bsplit(val, hh, ll);
        g_W3[ph] = hh; g_W3[ph + 16384] = ll;
    }
}

// =====================================================================
// Kernel 1: conv stack (thread per sample). Skips s==t blocks.
// conv1 s/t halves precomputed per-CTA into Rst (broadcast LDS);
// u/v halves stay per-thread in registers.
// =====================================================================
__global__ void __launch_bounds__(256) conv_kernel(
    const float* __restrict__ emb, const int* __restrict__ edges,
    const float* __restrict__ w1, const float* __restrict__ b1,
    const float* __restrict__ w2, const float* __restrict__ b2,
    const float* __restrict__ w3, const float* __restrict__ b3)
{
    int p = blockIdx.x;
    int s = p >> 5, t = p & 31;
    if (s == t) return;               // fc skips these tiles; output unused

    __shared__ float semb[N_NODES * D_EMB];
    __shared__ float sw1[48], sw2[48], sw3[48];
    __shared__ float sb1[4], sb2[4], sb3[4];
    __shared__ float Rst[188];        // [o*47 + pos]: bias + s-chan + t-chan
    int tid = threadIdx.x;
    for (int i = tid; i < N_NODES * D_EMB; i += 256) semb[i] = emb[i];
    if (tid < 48) { sw1[tid] = w1[tid]; sw2[tid] = w2[tid]; sw3[tid] = w3[tid]; }
    if (tid < 4)  { sb1[tid] = b1[tid]; sb2[tid] = b2[tid]; sb3[tid] = b3[tid]; }
    __syncthreads();

    // build Rst: 188 entries, 6 FMA each (s,t channels of conv1 + bias)
    if (tid < 188) {
        int o = tid / 47, i = tid - o * 47;
        const float* xs_ = semb + s * D_EMB + 2 * i;
        const float* xt_ = semb + t * D_EMB + 2 * i;
        const float* ws_ = sw1 + (o * 4 + 0) * 3;
        const float* wt_ = sw1 + (o * 4 + 1) * 3;
        Rst[tid] = sb1[o]
                 + ws_[0] * xs_[0] + ws_[1] * xs_[1] + ws_[2] * xs_[2]
                 + wt_[0] * xt_[0] + wt_[1] * xt_[1] + wt_[2] * xt_[2];
    }
    __syncthreads();

    int m = p * 256 + tid;
    int e = tid;
    int u = edges[2 * e], v = edges[2 * e + 1];
    const float* Xu = semb + u * D_EMB;
    const float* Xv = semb + v * D_EMB;

    // conv1 (u,v register part + Rst broadcast) + relu + pool2 -> 23
    float p1[4][23];
    #pragma unroll
    for (int i = 0; i < 23; i++) {
        float xu[5], xv[5];
        #pragma unroll
        for (int q = 0; q < 5; q++) { xu[q] = Xu[4 * i + q]; xv[q] = Xv[4 * i + q]; }
        #pragma unroll
        for (int o = 0; o < 4; o++) {
            float a0 = Rst[o * 47 + 2 * i];
            float a1 = Rst[o * 47 + 2 * i + 1];
            const float* wu = sw1 + (o * 4 + 2) * 3;
            const float* wv = sw1 + (o * 4 + 3) * 3;
            #pragma unroll
            for (int k = 0; k < 3; k++) {
                a0 = fmaf(wu[k], xu[k],     a0);
                a0 = fmaf(wv[k], xv[k],     a0);
                a1 = fmaf(wu[k], xu[k + 2], a1);
                a1 = fmaf(wv[k], xv[k + 2], a1);
            }
            p1[o][i] = fmaxf(fmaxf(a0, a1), 0.0f);  // relu(max) == max(relu)
        }
    }

    // conv2 (stride 1, 23->21) + relu + pool2 -> 10
    float p2[4][10];
    #pragma unroll
    for (int i = 0; i < 10; i++) {
        #pragma unroll
        for (int o = 0; o < 4; o++) {
            float a0 = sb2[o], a1 = sb2[o];
            #pragma unroll
            for (int c = 0; c < 4; c++)
                #pragma unroll
                for (int k = 0; k < 3; k++) {
                    float wv = sw2[(o * 4 + c) * 3 + k];
                    a0 = fmaf(wv, p1[c][2 * i + k],     a0);
                    a1 = fmaf(wv, p1[c][2 * i + 1 + k], a1);
                }
            p2[o][i] = fmaxf(fmaxf(a0, a1), 0.0f);
        }
    }
    // conv3 (10->8) + relu + pool2 -> 4; flatten [o*4 + pos]
    #pragma unroll
    for (int pos = 0; pos < 4; pos++) {
        #pragma unroll
        for (int o = 0; o < 4; o++) {
            float a0 = sb3[o], a1 = sb3[o];
            #pragma unroll
            for (int c = 0; c < 4; c++)
                #pragma unroll
                for (int k = 0; k < 3; k++) {
                    float wv = sw3[(o * 4 + c) * 3 + k];
                    a0 = fmaf(wv, p2[c][2 * pos + k],     a0);
                    a1 = fmaf(wv, p2[c][2 * pos + 1 + k], a1);
                }
            g_G[(o * 4 + pos) * M_TOT + m] = fmaxf(fmaxf(a0, a1), 0.0f);
        }
    }
}

// =====================================================================
// Kernel 2: fused FC chain on HMMA, cp.async double-buffered staging.
// =====================================================================
#define OFF_A2  0
#define OFF_A3  65536
#define OFF_WST 196608
#define FC_SMEM 229376

__device__ __forceinline__ void zero_acc(float acc[2][8][4]) {
    #pragma unroll
    for (int i = 0; i < 2; i++)
        #pragma unroll
        for (int j = 0; j < 8; j++)
            #pragma unroll
            for (int q = 0; q < 4; q++) acc[i][j][q] = 0.f;
}
__device__ __forceinline__ void mma_tile(float acc[2][8][4],
                                         uint32_t a[2][4], uint32_t b[4][4]) {
    #pragma unroll
    for (int i = 0; i < 2; i++)
        #pragma unroll
        for (int p = 0; p < 4; p++) {
            mma16816(acc[i][2 * p],     a[i], b[p][0], b[p][1]);
            mma16816(acc[i][2 * p + 1], a[i], b[p][2], b[p][3]);
        }
}
__device__ __forceinline__ void load_afrag(uint32_t base, int mb, int kb0, int rowb,
                                           int mi, int r8, uint32_t a[2][4]) {
    #pragma unroll
    for (int i = 0; i < 2; i++) {
        int m = mb + i * 16 + r8 + ((mi & 1) << 3);
        int kb = kb0 + ((mi >> 1) << 4);
        ldsm4(base + swz(m, kb, rowb), a[i]);
    }
}
__device__ __forceinline__ void load_bfrag(uint32_t base, int nb, int kb0, int rowb,
                                           int mi, int r8, uint32_t b[4][4]) {
    #pragma unroll
    for (int p = 0; p < 4; p++) {
        int n = nb + p * 16 + r8 + ((mi >> 1) << 3);
        int kb = kb0 + ((mi & 1) << 4);
        ldsm4(base + swz(n, kb, rowb), b[p]);
    }
}
__device__ __forceinline__ void store_pair(uint32_t hib, uint32_t lob, int m, int col,
                                           int rowb, float v0, float v1) {
    __nv_bfloat16 h0, l0, h1, l1;
    bsplit(v0, h0, l0); bsplit(v1, h1, l1);
    uint32_t off = swz(m, col * 2, rowb);
    sts32(hib + off, pk(h0, h1));
    sts32(lob + off, pk(l0, l1));
}
__device__ __forceinline__ void epilogue_act(float acc[2][8][4],
    uint32_t hib, uint32_t lob, int rowb, int mb, int nb, int kofs,
    const float* __restrict__ bias, int r4, int c4)
{
    #pragma unroll
    for (int i = 0; i < 2; i++)
        #pragma unroll
        for (int j = 0; j < 8; j++) {
            int col = nb + j * 8 + c4 * 2;
            int dc = kofs + col;
            float b0 = __ldg(bias + dc), b1 = __ldg(bias + dc + 1);
            int m = mb + i * 16 + r4;
            store_pair(hib, lob, m, dc, rowb,
                       fmaxf(acc[i][j][0] + b0, 0.f), fmaxf(acc[i][j][1] + b1, 0.f));
            store_pair(hib, lob, m + 8, dc, rowb,
                       fmaxf(acc[i][j][2] + b0, 0.f), fmaxf(acc[i][j][3] + b1, 0.f));
        }
}

__global__ void __launch_bounds__(256) fc_kernel(
    const float* __restrict__ fc1b, const float* __restrict__ fc2b,
    const float* __restrict__ fc3b, const float* __restrict__ fc4w,
    const float* __restrict__ fc4b)
{
    const int m0 = blockIdx.x * 128;
    const int pp = m0 >> 8;
    if ((pp >> 5) == (pp & 31)) return;   // masked tile: prop writes zeros itself

    extern __shared__ char sm[];
    const uint32_t smb = smem_u32(sm);
    const int tid = threadIdx.x;
    const int l = tid & 31, w = tid >> 5;
    const int wm = w & 3, wn = w >> 2;
    const int mb = wm * 32, nb = wn * 64;
    const int mi = l >> 3, r8 = l & 7;
    const int r4 = l >> 2, c4 = l & 3;

    const uint32_t A1h = smb + OFF_A3, A1l = A1h + 6144;
    const uint32_t W1h = A1h + 12288, W1l = A1h + 18432;
    const uint32_t A2h = smb + OFF_A2, A2l = A2h + 32768;
    const uint32_t A3h = smb + OFF_A3, A3l = A3h + 65536;
    const uint32_t WST = smb + OFF_WST;

    // pre-issue fc2 piece 0 into WST buf0 (hidden under fc1 staging/compute)
    stage16k(WST, g_W2, tid); CP_COMMIT();

    // ---- stage A1 (from g_G, padded kp=24) + W1 ----
    {
        __nv_bfloat16* a1h = (__nv_bfloat16*)(sm + OFF_A3);
        __nv_bfloat16* a1l = (__nv_bfloat16*)(sm + OFF_A3 + 6144);
        for (int idx = tid; idx < 2048; idx += 256) {
            int k = idx >> 7, m = idx & 127;
            float v = g_G[k * M_TOT + m0 + m];
            __nv_bfloat16 h, lo; bsplit(v, h, lo);
            a1h[m * 24 + k] = h; a1l[m * 24 + k] = lo;
        }
        copyg(sm + OFF_A3 + 12288, g_W1, 12288, tid);
    }
    __syncthreads();

    float acc[2][8][4];
    uint32_t ah[2][4], al[2][4], bh[4][4], bl[4][4];

    // ---- fc1: K=16, N=128 -> A2 ----
    zero_acc(acc);
    {
        #pragma unroll
        for (int i = 0; i < 2; i++) {
            int m = mb + i * 16 + r8 + ((mi & 1) << 3);
            int kb = (mi >> 1) << 4;
            ldsm4(A1h + m * 48 + kb, ah[i]);
            ldsm4(A1l + m * 48 + kb, al[i]);
        }
        #pragma unroll
        for (int p = 0; p < 4; p++) {
            int n = nb + p * 16 + r8 + ((mi >> 1) << 3);
            int kb = (mi & 1) << 4;
            ldsm4(W1h + n * 48 + kb, bh[p]);
            ldsm4(W1l + n * 48 + kb, bl[p]);
        }
        mma_tile(acc, ah, bh);
        mma_tile(acc, ah, bl);
        mma_tile(acc, al, bh);
    }
    epilogue_act(acc, A2h, A2l, 256, mb, nb, 0, fc1b, r4, c4);

    // ---- fc2: K=128, N=256. 8 pipelined pieces of 16KB: (h,c)->hi,lo ----
    #pragma unroll 1
    for (int ip = 0; ip < 8; ip++) {
        CP_WAIT0();
        __syncthreads();     // piece ip visible; all warps done with piece ip-1
        if (ip < 7) { stage16k(WST + ((ip + 1) & 1) * 16384, g_W2 + (ip + 1) * 8192, tid); CP_COMMIT(); }
        const int h = ip >> 2, c = (ip >> 1) & 1, term = ip & 1;
        if ((ip & 3) == 0) zero_acc(acc);
        const uint32_t wb = WST + (ip & 1) * 16384;
        #pragma unroll
        for (int ks = 0; ks < 4; ks++) {
            int kbA = (c * 64 + ks * 16) * 2;
            int kbW = ks * 32;
            if (term == 0) {
                load_afrag(A2h, mb, kbA, 256, mi, r8, ah);
                load_afrag(A2l, mb, kbA, 256, mi, r8, al);
                load_bfrag(wb, nb, kbW, 128, mi, r8, bh);
                mma_tile(acc, ah, bh);
                mma_tile(acc, al, bh);
            } else {
                load_afrag(A2h, mb, kbA, 256, mi, r8, ah);
                load_bfrag(wb, nb, kbW, 128, mi, r8, bl);
                mma_tile(acc, ah, bl);
            }
        }
        if (ip == 3) epilogue_act(acc, A3h, A3l, 512, mb, nb, 0,   fc2b, r4, c4);
        if (ip == 7) epilogue_act(acc, A3h, A3l, 512, mb, nb, 128, fc2b, r4, c4);
    }
    __syncthreads();   // all warps done reading A2 + fc2 epilogue written

    // ---- fc3: K=256, N=128. 4 pipelined pieces of 32KB in A2 region ----
    stage32k(smb + OFF_A2, g_W3, tid); CP_COMMIT();
    zero_acc(acc);
    #pragma unroll 1
    for (int ip = 0; ip < 4; ip++) {
        CP_WAIT0();
        __syncthreads();
        if (ip < 3) { stage32k(smb + OFF_A2 + ((ip + 1) & 1) * 32768, g_W3 + (ip + 1) * 16384, tid); CP_COMMIT(); }
        const int kh = ip >> 1, term = ip & 1;
        const uint32_t wb = smb + OFF_A2 + (ip & 1) * 32768;
        #pragma unroll
        for (int ks = 0; ks < 8; ks++) {
            int kbA = (kh * 128 + ks * 16) * 2;
            int kbW = ks * 32;
            if (term == 0) {
                load_afrag(A3h, mb, kbA, 512, mi, r8, ah);
                load_afrag(A3l, mb, kbA, 512, mi, r8, al);
                load_bfrag(wb, nb, kbW, 256, mi, r8, bh);
                mma_tile(acc, ah, bh);
                mma_tile(acc, al, bh);
            } else {
                load_afrag(A3h, mb, kbA, 512, mi, r8, ah);
                load_bfrag(wb, nb, kbW, 256, mi, r8, bl);
                mma_tile(acc, ah, bl);
            }
        }
    }

    // ---- fc4: bias+relu+dot in regs, quad-shfl reduce, smem combine ----
    float part[4] = {0.f, 0.f, 0.f, 0.f};
    #pragma unroll
    for (int i = 0; i < 2; i++)
        #pragma unroll
        for (int j = 0; j < 8; j++) {
            int col = nb + j * 8 + c4 * 2;
            float b0 = __ldg(fc3b + col), b1 = __ldg(fc3b + col + 1);
            float w0 = __ldg(fc4w + col), w1 = __ldg(fc4w + col + 1);
            part[i * 2 + 0] += fmaxf(acc[i][j][0] + b0, 0.f) * w0
                             + fmaxf(acc[i][j][1] + b1, 0.f) * w1;
            part[i * 2 + 1] += fmaxf(acc[i][j][2] + b0, 0.f) * w0
                             + fmaxf(acc[i][j][3] + b1, 0.f) * w1;
        }
    #pragma unroll
    for (int q = 0; q < 4; q++) {
        part[q] += __shfl_xor_sync(0xffffffff, part[q], 1);
        part[q] += __shfl_xor_sync(0xffffffff, part[q], 2);
    }
    float* red = (float*)(sm + OFF_WST);
    __syncthreads();
    if (c4 == 0) {
        #pragma unroll
        for (int i = 0; i < 2; i++) {
            red[wn * 128 + mb + i * 16 + r4]     = part[i * 2];
            red[wn * 128 + mb + i * 16 + r4 + 8] = part[i * 2 + 1];
        }
    }
    __syncthreads();
    if (tid < 128) {
        float v = red[tid] + red[128 + tid] + __ldg(fc4b);
        g_preds[m0 + tid] = v;
    }
}

// =====================================================================
// Kernel 3: 3-step propagation, block per p. Deterministic.
// =====================================================================
__global__ void __launch_bounds__(256) prop_kernel(const int* __restrict__ edges)
{
    __shared__ float xs[32];
    __shared__ float xn[8][32];
    __shared__ float acc[32];
    __shared__ float pr[256];
    __shared__ int   su[256], sv[256];
    int tid = threadIdx.x;
    int p = blockIdx.x;
    int s = p >> 5, t = p & 31;
    su[tid] = edges[2 * tid];
    sv[tid] = edges[2 * tid + 1];
    if (s != t) pr[tid] = g_preds[p * 256 + tid];
    if (tid < 32) { xs[tid] = (tid == s) ? 1.0f : 0.0f; acc[tid] = 0.0f; }
    __syncthreads();
    if (s != t) {
        int j = tid & 31, grp = tid >> 5;
        for (int step = 0; step < 3; step++) {
            float sum = 0.0f;
            #pragma unroll 4
            for (int q = 0; q < 32; q++) {
                int e = grp * 32 + q;
                sum += (sv[e] == j) ? xs[su[e]] * pr[e] : 0.0f;
            }
            xn[grp][j] = sum;
            __syncthreads();
            if (tid < 32) {
                float v = 0.0f;
                #pragma unroll
                for (int g2 = 0; g2 < 8; g2++) v += xn[g2][tid];
                xs[tid] = v;
                acc[tid] += v;
            }
            __syncthreads();
        }
    }
    if (tid < 32) g_part[p * 32 + tid] = acc[tid];
}

// =====================================================================
// Kernel 4: final reduction + normalize.
// =====================================================================
__global__ void __launch_bounds__(1024) reduce_kernel(float* __restrict__ out)
{
    __shared__ float red[32][32];
    __shared__ float rbc[32];
    __shared__ float tot;
    int tid = threadIdx.x;
    int j = tid & 31, chunk = tid >> 5;
    float sum = 0.0f;
    for (int q = 0; q < 32; q++)
        sum += g_part[(chunk * 32 + q) * 32 + j];
    red[chunk][j] = sum;
    __syncthreads();
    if (tid < 32) {
        float v = 0.0f;
        for (int c = 0; c < 32; c++) v += red[c][tid];
        rbc[tid] = v;
    }
    __syncthreads();
    if (tid == 0) {
        float tt = 0.0f;
        for (int k = 0; k < 32; k++) tt += rbc[k];
        tot = tt;
    }
    __syncthreads();
    if (tid < 32) out[tid] = rbc[tid] / tot;
}

// =====================================================================
extern "C" void kernel_launch(void* const* d_in, const int* in_sizes, int n_in,
                              void* d_out, int out_size)
{
    const float* emb   = (const float*)d_in[0];
    const int*   edges = (const int*)  d_in[1];
    const float* w1    = (const float*)d_in[2];
    const float* b1    = (const float*)d_in[3];
    const float* w2    = (const float*)d_in[4];
    const float* b2    = (const float*)d_in[5];
    const float* w3    = (const float*)d_in[6];
    const float* b3    = (const float*)d_in[7];
    const float* fc1w  = (const float*)d_in[8];
    const float* fc1b  = (const float*)d_in[9];
    const float* fc2w  = (const float*)d_in[10];
    const float* fc2b  = (const float*)d_in[11];
    const float* fc3w  = (const float*)d_in[12];
    const float* fc3b  = (const float*)d_in[13];
    const float* fc4w  = (const float*)d_in[14];
    const float* fc4b  = (const float*)d_in[15];

    prep_kernel<<<268, 256>>>(fc1w, fc2w, fc3w);

    conv_kernel<<<P_PAIRS, 256>>>(emb, edges, w1, b1, w2, b2, w3, b3);

    cudaFuncSetAttribute(fc_kernel, cudaFuncAttributeMaxDynamicSharedMemorySize, FC_SMEM);
    fc_kernel<<<M_TOT / 128, 256, FC_SMEM>>>(fc1b, fc2b, fc3b, fc4w, fc4b);

    prop_kernel<<<P_PAIRS, 256>>>(edges);
    reduce_kernel<<<1, 1024>>>((float*)d_out);
}

// round 16
// speedup vs baseline: 1.1209x; 1.0716x over previous
#include <cuda_runtime.h>
#include <cuda_bf16.h>
#include <cstdint>

#define N_NODES 32
#define D_EMB   96
#define EPAD    97      // padded smem row stride: gcd(97,32)=1 kills bank conflicts
#define P_PAIRS 1024
#define M_TOT   262144   // P_PAIRS * 256

// ---- scratch (device globals: no allocations allowed) ----
__device__ float g_G[16 * M_TOT];       // conv features [feature][sample]
__device__ float g_preds[M_TOT];
__device__ float g_part[P_PAIRS * 32];
// weight images: bf16 hi/lo, pre-transposed [n][k], pre-swizzled (W2/W3)
__device__ __align__(16) __nv_bfloat16 g_W1[6144];    // [n=128][kp=24] hi | lo
__device__ __align__(16) __nv_bfloat16 g_W2[131072];  // 8 pieces of 8192: (h,c)->hi,lo
__device__ __align__(16) __nv_bfloat16 g_W3[65536];   // 4 pieces of 16384: (kh)->hi,lo

// ---------------- helpers ----------------
__device__ __forceinline__ uint32_t smem_u32(const void* p) {
    uint32_t a;
    asm("{ .reg .u64 t; cvta.to.shared.u64 t, %1; cvt.u32.u64 %0, t; }" : "=r"(a) : "l"(p));
    return a;
}
__device__ __forceinline__ uint32_t swz(int m, int kb, int rowb) {
    return (uint32_t)(m * rowb + (kb ^ ((m & 7) << 4)));
}
__device__ __forceinline__ void ldsm4(uint32_t a, uint32_t* r) {
    asm volatile("ldmatrix.sync.aligned.m8n8.x4.shared.b16 {%0,%1,%2,%3}, [%4];"
        : "=r"(r[0]), "=r"(r[1]), "=r"(r[2]), "=r"(r[3]) : "r"(a));
}
__device__ __forceinline__ void mma16816(float* c, const uint32_t* a, uint32_t b0, uint32_t b1) {
    asm volatile("mma.sync.aligned.m16n8k16.row.col.f32.bf16.bf16.f32 "
        "{%0,%1,%2,%3}, {%4,%5,%6,%7}, {%8,%9}, {%0,%1,%2,%3};"
        : "+f"(c[0]), "+f"(c[1]), "+f"(c[2]), "+f"(c[3])
        : "r"(a[0]), "r"(a[1]), "r"(a[2]), "r"(a[3]), "r"(b0), "r"(b1));
}
__device__ __forceinline__ void bsplit(float x, __nv_bfloat16& h, __nv_bfloat16& l) {
    h = __float2bfloat16_rn(x);
    l = __float2bfloat16_rn(x - __bfloat162float(h));
}
__device__ __forceinline__ uint32_t pk(__nv_bfloat16 lo, __nv_bfloat16 hi) {
    return (uint32_t)__bfloat16_as_ushort(hi) << 16 | (uint32_t)__bfloat16_as_ushort(lo);
}
__device__ __forceinline__ void sts32(uint32_t addr, uint32_t v) {
    asm volatile("st.shared.b32 [%0], %1;" :: "r"(addr), "r"(v) : "memory");
}
__device__ __forceinline__ void copyg(void* dst, const __nv_bfloat16* src, int bytes, int tid) {
    float4* d = (float4*)dst; const float4* s = (const float4*)src;
    for (int i = tid; i < (bytes >> 4); i += 256) d[i] = s[i];
}
// ---- cp.async (LDGSTS) ----
__device__ __forceinline__ void cpa16(uint32_t saddr, const void* g) {
    asm volatile("cp.async.cg.shared.global [%0], [%1], 16;" :: "r"(saddr), "l"(g) : "memory");
}
#define CP_COMMIT() asm volatile("cp.async.commit_group;" ::: "memory")
#define CP_WAIT0()  asm volatile("cp.async.wait_group 0;" ::: "memory")
__device__ __forceinline__ void stage16k(uint32_t sbuf, const __nv_bfloat16* src, int tid) {
    #pragma unroll
    for (int i = 0; i < 4; i++) {
        int idx = tid + i * 256;
        cpa16(sbuf + idx * 16, (const char*)src + idx * 16);
    }
}
__device__ __forceinline__ void stage32k(uint32_t sbuf, const __nv_bfloat16* src, int tid) {
    #pragma unroll
    for (int i = 0; i < 8; i++) {
        int idx = tid + i * 256;
        cpa16(sbuf + idx * 16, (const char*)src + idx * 16);
    }
}

// =====================================================================
// Kernel 0: prep — split weights to bf16 hi/lo images
// =====================================================================
__global__ void __launch_bounds__(256) prep_kernel(
    const float* __restrict__ fc1w, const float* __restrict__ fc2w,
    const float* __restrict__ fc3w)
{
    int idx = blockIdx.x * 256 + threadIdx.x;   // 0 .. 68607
    if (idx < 3072) {                 // W1: [n=128][kp=24], linear (padded)
        int n = idx / 24, k = idx % 24;
        float val = (k < 16) ? fc1w[k * 128 + n] : 0.0f;
        __nv_bfloat16 hh, ll; bsplit(val, hh, ll);
        g_W1[n * 24 + k] = hh; g_W1[3072 + n * 24 + k] = ll;
    } else if (idx < 35840) {         // W2: pieces [(h*2+c)]: hi 8192 | lo 8192, rowb=128
        int j = idx - 3072;
        int h = j >> 14, c = (j >> 13) & 1;
        int j2 = j & 8191;
        int n = j2 >> 6, k = j2 & 63;
        float val = fc2w[(c * 64 + k) * 256 + h * 128 + n];
        int eo = n * 64 + (((k * 2) ^ ((n & 7) << 4)) >> 1);
        int ph = (h * 2 + c) * 16384 + eo;
        __nv_bfloat16 hh, ll; bsplit(val, hh, ll);
        g_W2[ph] = hh; g_W2[ph + 8192] = ll;
    } else {                          // W3: k-halves, [128n][128k] rowb=256 swizzle
        int j = idx - 35840;          // 0..32767
        int n = j >> 8, k = j & 255;
        int kh = k >> 7, kl = k & 127;
        float val = fc3w[k * 128 + n];
        int eo = n * 128 + (((kl * 2) ^ ((n & 7) << 4)) >> 1);
        int ph = kh * 32768 + eo;
        __nv_bfloat16 hh, ll; bsplit(val, hh, ll);
        g_W3[ph] = hh; g_W3[ph + 16384] = ll;
    }
}

// =====================================================================
// Kernel 1: conv stack (thread per sample). Skips s==t blocks.
// semb rows padded to 97 floats -> per-lane random-u loads spread banks.
// conv1 s/t halves precomputed per-CTA into Rst (broadcast LDS).
// =====================================================================
__global__ void __launch_bounds__(256) conv_kernel(
    const float* __restrict__ emb, const int* __restrict__ edges,
    const float* __restrict__ w1, const float* __restrict__ b1,
    const float* __restrict__ w2, const float* __restrict__ b2,
    const float* __restrict__ w3, const float* __restrict__ b3)
{
    int p = blockIdx.x;
    int s = p >> 5, t = p & 31;
    if (s == t) return;               // fc skips these tiles; output unused

    __shared__ float semb[N_NODES * EPAD];
    __shared__ float sw1[48], sw2[48], sw3[48];
    __shared__ float sb1[4], sb2[4], sb3[4];
    __shared__ float Rst[188];        // [o*47 + pos]: bias + s-chan + t-chan
    int tid = threadIdx.x;
    for (int i = tid; i < N_NODES * D_EMB; i += 256) {
        int n = i / D_EMB, d = i - n * D_EMB;
        semb[n * EPAD + d] = emb[i];
    }
    if (tid < 48) { sw1[tid] = w1[tid]; sw2[tid] = w2[tid]; sw3[tid] = w3[tid]; }
    if (tid < 4)  { sb1[tid] = b1[tid]; sb2[tid] = b2[tid]; sb3[tid] = b3[tid]; }
    __syncthreads();

    // build Rst: 188 entries, 6 FMA each (s,t channels of conv1 + bias)
    if (tid < 188) {
        int o = tid / 47, i = tid - o * 47;
        const float* xs_ = semb + s * EPAD + 2 * i;
        const float* xt_ = semb + t * EPAD + 2 * i;
        const float* ws_ = sw1 + (o * 4 + 0) * 3;
        const float* wt_ = sw1 + (o * 4 + 1) * 3;
        Rst[tid] = sb1[o]
                 + ws_[0] * xs_[0] + ws_[1] * xs_[1] + ws_[2] * xs_[2]
                 + wt_[0] * xt_[0] + wt_[1] * xt_[1] + wt_[2] * xt_[2];
    }
    __syncthreads();

    int m = p * 256 + tid;
    int e = tid;
    int u = edges[2 * e], v = edges[2 * e + 1];
    const float* Xu = semb + u * EPAD;
    const float* Xv = semb + v * EPAD;

    // conv1 (u,v register part + Rst broadcast) + relu + pool2 -> 23
    float p1[4][23];
    #pragma unroll
    for (int i = 0; i < 23; i++) {
        float xu[5], xv[5];
        #pragma unroll
        for (int q = 0; q < 5; q++) { xu[q] = Xu[4 * i + q]; xv[q] = Xv[4 * i + q]; }
        #pragma unroll
        for (int o = 0; o < 4; o++) {
            float a0 = Rst[o * 47 + 2 * i];
            float a1 = Rst[o * 47 + 2 * i + 1];
            const float* wu = sw1 + (o * 4 + 2) * 3;
            const float* wv = sw1 + (o * 4 + 3) * 3;
            #pragma unroll
            for (int k = 0; k < 3; k++) {
                a0 = fmaf(wu[k], xu[k],     a0);
                a0 = fmaf(wv[k], xv[k],     a0);
                a1 = fmaf(wu[k], xu[k + 2], a1);
                a1 = fmaf(wv[k], xv[k + 2], a1);
            }
            p1[o][i] = fmaxf(fmaxf(a0, a1), 0.0f);  // relu(max) == max(relu)
        }
    }

    // conv2 (stride 1, 23->21) + relu + pool2 -> 10
    float p2[4][10];
    #pragma unroll
    for (int i = 0; i < 10; i++) {
        #pragma unroll
        for (int o = 0; o < 4; o++) {
            float a0 = sb2[o], a1 = sb2[o];
            #pragma unroll
            for (int c = 0; c < 4; c++)
                #pragma unroll
                for (int k = 0; k < 3; k++) {
                    float wv = sw2[(o * 4 + c) * 3 + k];
                    a0 = fmaf(wv, p1[c][2 * i + k],     a0);
                    a1 = fmaf(wv, p1[c][2 * i + 1 + k], a1);
                }
            p2[o][i] = fmaxf(fmaxf(a0, a1), 0.0f);
        }
    }
    // conv3 (10->8) + relu + pool2 -> 4; flatten [o*4 + pos]
    #pragma unroll
    for (int pos = 0; pos < 4; pos++) {
        #pragma unroll
        for (int o = 0; o < 4; o++) {
            float a0 = sb3[o], a1 = sb3[o];
            #pragma unroll
            for (int c = 0; c < 4; c++)
                #pragma unroll
                for (int k = 0; k < 3; k++) {
                    float wv = sw3[(o * 4 + c) * 3 + k];
                    a0 = fmaf(wv, p2[c][2 * pos + k],     a0);
                    a1 = fmaf(wv, p2[c][2 * pos + 1 + k], a1);
                }
            g_G[(o * 4 + pos) * M_TOT + m] = fmaxf(fmaxf(a0, a1), 0.0f);
        }
    }
}

// =====================================================================
// Kernel 2: fused FC chain on HMMA, cp.async double-buffered staging.
// =====================================================================
#define OFF_A2  0
#define OFF_A3  65536
#define OFF_WST 196608
#define FC_SMEM 229376

__device__ __forceinline__ void zero_acc(float acc[2][8][4]) {
    #pragma unroll
    for (int i = 0; i < 2; i++)
        #pragma unroll
        for (int j = 0; j < 8; j++)
            #pragma unroll
            for (int q = 0; q < 4; q++) acc[i][j][q] = 0.f;
}
__device__ __forceinline__ void mma_tile(float acc[2][8][4],
                                         uint32_t a[2][4], uint32_t b[4][4]) {
    #pragma unroll
    for (int i = 0; i < 2; i++)
        #pragma unroll
        for (int p = 0; p < 4; p++) {
            mma16816(acc[i][2 * p],     a[i], b[p][0], b[p][1]);
            mma16816(acc[i][2 * p + 1], a[i], b[p][2], b[p][3]);
        }
}
__device__ __forceinline__ void load_afrag(uint32_t base, int mb, int kb0, int rowb,
                                           int mi, int r8, uint32_t a[2][4]) {
    #pragma unroll
    for (int i = 0; i < 2; i++) {
        int m = mb + i * 16 + r8 + ((mi & 1) << 3);
        int kb = kb0 + ((mi >> 1) << 4);
        ldsm4(base + swz(m, kb, rowb), a[i]);
    }
}
__device__ __forceinline__ void load_bfrag(uint32_t base, int nb, int kb0, int rowb,
                                           int mi, int r8, uint32_t b[4][4]) {
    #pragma unroll
    for (int p = 0; p < 4; p++) {
        int n = nb + p * 16 + r8 + ((mi >> 1) << 3);
        int kb = kb0 + ((mi & 1) << 4);
        ldsm4(base + swz(n, kb, rowb), b[p]);
    }
}
__device__ __forceinline__ void store_pair(uint32_t hib, uint32_t lob, int m, int col,
                                           int rowb, float v0, float v1) {
    __nv_bfloat16 h0, l0, h1, l1;
    bsplit(v0, h0, l0); bsplit(v1, h1, l1);
    uint32_t off = swz(m, col * 2, rowb);
    sts32(hib + off, pk(h0, h1));
    sts32(lob + off, pk(l0, l1));
}
__device__ __forceinline__ void epilogue_act(float acc[2][8][4],
    uint32_t hib, uint32_t lob, int rowb, int mb, int nb, int kofs,
    const float* __restrict__ bias, int r4, int c4)
{
    #pragma unroll
    for (int i = 0; i < 2; i++)
        #pragma unroll
        for (int j = 0; j < 8; j++) {
            int col = nb + j * 8 + c4 * 2;
            int dc = kofs + col;
            float b0 = __ldg(bias + dc), b1 = __ldg(bias + dc + 1);
            int m = mb + i * 16 + r4;
            store_pair(hib, lob, m, dc, rowb,
                       fmaxf(acc[i][j][0] + b0, 0.f), fmaxf(acc[i][j][1] + b1, 0.f));
            store_pair(hib, lob, m + 8, dc, rowb,
                       fmaxf(acc[i][j][2] + b0, 0.f), fmaxf(acc[i][j][3] + b1, 0.f));
        }
}

__global__ void __launch_bounds__(256) fc_kernel(
    const float* __restrict__ fc1b, const float* __restrict__ fc2b,
    const float* __restrict__ fc3b, const float* __restrict__ fc4w,
    const float* __restrict__ fc4b)
{
    const int m0 = blockIdx.x * 128;
    const int pp = m0 >> 8;
    if ((pp >> 5) == (pp & 31)) return;   // masked tile: prop writes zeros itself

    extern __shared__ char sm[];
    const uint32_t smb = smem_u32(sm);
    const int tid = threadIdx.x;
    const int l = tid & 31, w = tid >> 5;
    const int wm = w & 3, wn = w >> 2;
    const int mb = wm * 32, nb = wn * 64;
    const int mi = l >> 3, r8 = l & 7;
    const int r4 = l >> 2, c4 = l & 3;

    const uint32_t A1h = smb + OFF_A3, A1l = A1h + 6144;
    const uint32_t W1h = A1h + 12288, W1l = A1h + 18432;
    const uint32_t A2h = smb + OFF_A2, A2l = A2h + 32768;
    const uint32_t A3h = smb + OFF_A3, A3l = A3h + 65536;
    const uint32_t WST = smb + OFF_WST;

    // pre-issue fc2 piece 0 into WST buf0 (hidden under fc1 staging/compute)
    stage16k(WST, g_W2, tid); CP_COMMIT();

    // ---- stage A1 (from g_G, padded kp=24) + W1 ----
    {
        __nv_bfloat16* a1h = (__nv_bfloat16*)(sm + OFF_A3);
        __nv_bfloat16* a1l = (__nv_bfloat16*)(sm + OFF_A3 + 6144);
        for (int idx = tid; idx < 2048; idx += 256) {
            int k = idx >> 7, m = idx & 127;
            float v = g_G[k * M_TOT + m0 + m];
            __nv_bfloat16 h, lo; bsplit(v, h, lo);
            a1h[m * 24 + k] = h; a1l[m * 24 + k] = lo;
        }
        copyg(sm + OFF_A3 + 12288, g_W1, 12288, tid);
    }
    __syncthreads();

    float acc[2][8][4];
    uint32_t ah[2][4], al[2][4], bh[4][4], bl[4][4];

    // ---- fc1: K=16, N=128 -> A2 ----
    zero_acc(acc);
    {
        #pragma unroll
        for (int i = 0; i < 2; i++) {
            int m = mb + i * 16 + r8 + ((mi & 1) << 3);
            int kb = (mi >> 1) << 4;
            ldsm4(A1h + m * 48 + kb, ah[i]);
            ldsm4(A1l + m * 48 + kb, al[i]);
        }
        #pragma unroll
        for (int p = 0; p < 4; p++) {
            int n = nb + p * 16 + r8 + ((mi >> 1) << 3);
            int kb = (mi & 1) << 4;
            ldsm4(W1h + n * 48 + kb, bh[p]);
            ldsm4(W1l + n * 48 + kb, bl[p]);
        }
        mma_tile(acc, ah, bh);
        mma_tile(acc, ah, bl);
        mma_tile(acc, al, bh);
    }
    epilogue_act(acc, A2h, A2l, 256, mb, nb, 0, fc1b, r4, c4);

    // ---- fc2: K=128, N=256. 8 pipelined pieces of 16KB: (h,c)->hi,lo ----
    #pragma unroll 1
    for (int ip = 0; ip < 8; ip++) {
        CP_WAIT0();
        __syncthreads();     // piece ip visible; all warps done with piece ip-1
        if (ip < 7) { stage16k(WST + ((ip + 1) & 1) * 16384, g_W2 + (ip + 1) * 8192, tid); CP_COMMIT(); }
        const int h = ip >> 2, c = (ip >> 1) & 1, term = ip & 1;
        if ((ip & 3) == 0) zero_acc(acc);
        const uint32_t wb = WST + (ip & 1) * 16384;
        #pragma unroll
        for (int ks = 0; ks < 4; ks++) {
            int kbA = (c * 64 + ks * 16) * 2;
            int kbW = ks * 32;
            if (term == 0) {
                load_afrag(A2h, mb, kbA, 256, mi, r8, ah);
                load_afrag(A2l, mb, kbA, 256, mi, r8, al);
                load_bfrag(wb, nb, kbW, 128, mi, r8, bh);
                mma_tile(acc, ah, bh);
                mma_tile(acc, al, bh);
            } else {
                load_afrag(A2h, mb, kbA, 256, mi, r8, ah);
                load_bfrag(wb, nb, kbW, 128, mi, r8, bl);
                mma_tile(acc, ah, bl);
            }
        }
        if (ip == 3) epilogue_act(acc, A3h, A3l, 512, mb, nb, 0,   fc2b, r4, c4);
        if (ip == 7) epilogue_act(acc, A3h, A3l, 512, mb, nb, 128, fc2b, r4, c4);
    }
    __syncthreads();   // all warps done reading A2 + fc2 epilogue written

    // ---- fc3: K=256, N=128. 4 pipelined pieces of 32KB in A2 region ----
    stage32k(smb + OFF_A2, g_W3, tid); CP_COMMIT();
    zero_acc(acc);
    #pragma unroll 1
    for (int ip = 0; ip < 4; ip++) {
        CP_WAIT0();
        __syncthreads();
        if (ip < 3) { stage32k(smb + OFF_A2 + ((ip + 1) & 1) * 32768, g_W3 + (ip + 1) * 16384, tid); CP_COMMIT(); }
        const int kh = ip >> 1, term = ip & 1;
        const uint32_t wb = smb + OFF_A2 + (ip & 1) * 32768;
        #pragma unroll
        for (int ks = 0; ks < 8; ks++) {
            int kbA = (kh * 128 + ks * 16) * 2;
            int kbW = ks * 32;
            if (term == 0) {
                load_afrag(A3h, mb, kbA, 512, mi, r8, ah);
                load_afrag(A3l, mb, kbA, 512, mi, r8, al);
                load_bfrag(wb, nb, kbW, 256, mi, r8, bh);
                mma_tile(acc, ah, bh);
                mma_tile(acc, al, bh);
            } else {
                load_afrag(A3h, mb, kbA, 512, mi, r8, ah);
                load_bfrag(wb, nb, kbW, 256, mi, r8, bl);
                mma_tile(acc, ah, bl);
            }
        }
    }

    // ---- fc4: bias+relu+dot in regs, quad-shfl reduce, smem combine ----
    float part[4] = {0.f, 0.f, 0.f, 0.f};
    #pragma unroll
    for (int i = 0; i < 2; i++)
        #pragma unroll
        for (int j = 0; j < 8; j++) {
            int col = nb + j * 8 + c4 * 2;
            float b0 = __ldg(fc3b + col), b1 = __ldg(fc3b + col + 1);
            float w0 = __ldg(fc4w + col), w1 = __ldg(fc4w + col + 1);
            part[i * 2 + 0] += fmaxf(acc[i][j][0] + b0, 0.f) * w0
                             + fmaxf(acc[i][j][1] + b1, 0.f) * w1;
            part[i * 2 + 1] += fmaxf(acc[i][j][2] + b0, 0.f) * w0
                             + fmaxf(acc[i][j][3] + b1, 0.f) * w1;
        }
    #pragma unroll
    for (int q = 0; q < 4; q++) {
        part[q] += __shfl_xor_sync(0xffffffff, part[q], 1);
        part[q] += __shfl_xor_sync(0xffffffff, part[q], 2);
    }
    float* red = (float*)(sm + OFF_WST);
    __syncthreads();
    if (c4 == 0) {
        #pragma unroll
        for (int i = 0; i < 2; i++) {
            red[wn * 128 + mb + i * 16 + r4]     = part[i * 2];
            red[wn * 128 + mb + i * 16 + r4 + 8] = part[i * 2 + 1];
        }
    }
    __syncthreads();
    if (tid < 128) {
        float v = red[tid] + red[128 + tid] + __ldg(fc4b);
        g_preds[m0 + tid] = v;
    }
}

// =====================================================================
// Kernel 3: 3-step propagation, block per p. Deterministic.
// =====================================================================
__global__ void __launch_bounds__(256) prop_kernel(const int* __restrict__ edges)
{
    __shared__ float xs[32];
    __shared__ float xn[8][32];
    __shared__ float acc[32];
    __shared__ float pr[256];
    __shared__ int   su[256], sv[256];
    int tid = threadIdx.x;
    int p = blockIdx.x;
    int s = p >> 5, t = p & 31;
    su[tid] = edges[2 * tid];
    sv[tid] = edges[2 * tid + 1];
    if (s != t) pr[tid] = g_preds[p * 256 + tid];
    if (tid < 32) { xs[tid] = (tid == s) ? 1.0f : 0.0f; acc[tid] = 0.0f; }
    __syncthreads();
    if (s != t) {
        int j = tid & 31, grp = tid >> 5;
        for (int step = 0; step < 3; step++) {
            float sum = 0.0f;
            #pragma unroll 4
            for (int q = 0; q < 32; q++) {
                int e = grp * 32 + q;
                sum += (sv[e] == j) ? xs[su[e]] * pr[e] : 0.0f;
            }
            xn[grp][j] = sum;
            __syncthreads();
            if (tid < 32) {
                float v = 0.0f;
                #pragma unroll
                for (int g2 = 0; g2 < 8; g2++) v += xn[g2][tid];
                xs[tid] = v;
                acc[tid] += v;
            }
            __syncthreads();
        }
    }
    if (tid < 32) g_part[p * 32 + tid] = acc[tid];
}

// =====================================================================
// Kernel 4: final reduction + normalize.
// =====================================================================
__global__ void __launch_bounds__(1024) reduce_kernel(float* __restrict__ out)
{
    __shared__ float red[32][32];
    __shared__ float rbc[32];
    __shared__ float tot;
    int tid = threadIdx.x;
    int j = tid & 31, chunk = tid >> 5;
    float sum = 0.0f;
    for (int q = 0; q < 32; q++)
        sum += g_part[(chunk * 32 + q) * 32 + j];
    red[chunk][j] = sum;
    __syncthreads();
    if (tid < 32) {
        float v = 0.0f;
        for (int c = 0; c < 32; c++) v += red[c][tid];
        rbc[tid] = v;
    }
    __syncthreads();
    if (tid == 0) {
        float tt = 0.0f;
        for (int k = 0; k < 32; k++) tt += rbc[k];
        tot = tt;
    }
    __syncthreads();
    if (tid < 32) out[tid] = rbc[tid] / tot;
}

// =====================================================================
extern "C" void kernel_launch(void* const* d_in, const int* in_sizes, int n_in,
                              void* d_out, int out_size)
{
    const float* emb   = (const float*)d_in[0];
    const int*   edges = (const int*)  d_in[1];
    const float* w1    = (const float*)d_in[2];
    const float* b1    = (const float*)d_in[3];
    const float* w2    = (const float*)d_in[4];
    const float* b2    = (const float*)d_in[5];
    const float* w3    = (const float*)d_in[6];
    const float* b3    = (const float*)d_in[7];
    const float* fc1w  = (const float*)d_in[8];
    const float* fc1b  = (const float*)d_in[9];
    const float* fc2w  = (const float*)d_in[10];
    const float* fc2b  = (const float*)d_in[11];
    const float* fc3w  = (const float*)d_in[12];
    const float* fc3b  = (const float*)d_in[13];
    const float* fc4w  = (const float*)d_in[14];
    const float* fc4b  = (const float*)d_in[15];

    prep_kernel<<<268, 256>>>(fc1w, fc2w, fc3w);

    conv_kernel<<<P_PAIRS, 256>>>(emb, edges, w1, b1, w2, b2, w3, b3);

    cudaFuncSetAttribute(fc_kernel, cudaFuncAttributeMaxDynamicSharedMemorySize, FC_SMEM);
    fc_kernel<<<M_TOT / 128, 256, FC_SMEM>>>(fc1b, fc2b, fc3b, fc4w, fc4b);

    prop_kernel<<<P_PAIRS, 256>>>(edges);
    reduce_kernel<<<1, 1024>>>((float*)d_out);
}

// round 17
// speedup vs baseline: 1.1258x; 1.0044x over previous
#include <cuda_runtime.h>
#include <cuda_bf16.h>
#include <cstdint>

#define N_NODES 32
#define D_EMB   96
#define P_PAIRS 1024
#define M_TOT   262144   // P_PAIRS * 256

// ---- scratch (device globals: no allocations allowed) ----
__device__ float g_G[16 * M_TOT];       // conv features [feature][sample]
__device__ float g_preds[M_TOT];
__device__ float g_part[P_PAIRS * 32];
__device__ float g_Cuv[188 * 256];      // conv1 u,v-part: [oi][e], e fastest
// weight images: bf16 hi/lo, pre-transposed [n][k], pre-swizzled (W2/W3)
__device__ __align__(16) __nv_bfloat16 g_W1[6144];    // [n=128][kp=24] hi | lo
__device__ __align__(16) __nv_bfloat16 g_W2[131072];  // 8 pieces of 8192: (h,c)->hi,lo
__device__ __align__(16) __nv_bfloat16 g_W3[65536];   // 4 pieces of 16384: (kh)->hi,lo

// ---------------- helpers ----------------
__device__ __forceinline__ uint32_t smem_u32(const void* p) {
    uint32_t a;
    asm("{ .reg .u64 t; cvta.to.shared.u64 t, %1; cvt.u32.u64 %0, t; }" : "=r"(a) : "l"(p));
    return a;
}
__device__ __forceinline__ uint32_t swz(int m, int kb, int rowb) {
    return (uint32_t)(m * rowb + (kb ^ ((m & 7) << 4)));
}
__device__ __forceinline__ void ldsm4(uint32_t a, uint32_t* r) {
    asm volatile("ldmatrix.sync.aligned.m8n8.x4.shared.b16 {%0,%1,%2,%3}, [%4];"
        : "=r"(r[0]), "=r"(r[1]), "=r"(r[2]), "=r"(r[3]) : "r"(a));
}
__device__ __forceinline__ void mma16816(float* c, const uint32_t* a, uint32_t b0, uint32_t b1) {
    asm volatile("mma.sync.aligned.m16n8k16.row.col.f32.bf16.bf16.f32 "
        "{%0,%1,%2,%3}, {%4,%5,%6,%7}, {%8,%9}, {%0,%1,%2,%3};"
        : "+f"(c[0]), "+f"(c[1]), "+f"(c[2]), "+f"(c[3])
        : "r"(a[0]), "r"(a[1]), "r"(a[2]), "r"(a[3]), "r"(b0), "r"(b1));
}
__device__ __forceinline__ void bsplit(float x, __nv_bfloat16& h, __nv_bfloat16& l) {
    h = __float2bfloat16_rn(x);
    l = __float2bfloat16_rn(x - __bfloat162float(h));
}
__device__ __forceinline__ uint32_t pk(__nv_bfloat16 lo, __nv_bfloat16 hi) {
    return (uint32_t)__bfloat16_as_ushort(hi) << 16 | (uint32_t)__bfloat16_as_ushort(lo);
}
__device__ __forceinline__ void sts32(uint32_t addr, uint32_t v) {
    asm volatile("st.shared.b32 [%0], %1;" :: "r"(addr), "r"(v) : "memory");
}
__device__ __forceinline__ void copyg(void* dst, const __nv_bfloat16* src, int bytes, int tid) {
    float4* d = (float4*)dst; const float4* s = (const float4*)src;
    for (int i = tid; i < (bytes >> 4); i += 256) d[i] = s[i];
}
// ---- cp.async (LDGSTS) ----
__device__ __forceinline__ void cpa16(uint32_t saddr, const void* g) {
    asm volatile("cp.async.cg.shared.global [%0], [%1], 16;" :: "r"(saddr), "l"(g) : "memory");
}
#define CP_COMMIT() asm volatile("cp.async.commit_group;" ::: "memory")
#define CP_WAIT0()  asm volatile("cp.async.wait_group 0;" ::: "memory")
__device__ __forceinline__ void stage16k(uint32_t sbuf, const __nv_bfloat16* src, int tid) {
    #pragma unroll
    for (int i = 0; i < 4; i++) {
        int idx = tid + i * 256;
        cpa16(sbuf + idx * 16, (const char*)src + idx * 16);
    }
}
__device__ __forceinline__ void stage32k(uint32_t sbuf, const __nv_bfloat16* src, int tid) {
    #pragma unroll
    for (int i = 0; i < 8; i++) {
        int idx = tid + i * 256;
        cpa16(sbuf + idx * 16, (const char*)src + idx * 16);
    }
}

// =====================================================================
// Kernel 0: prep — split weights to bf16 hi/lo images + Cuv table.
// grid 456*256 = 116736 = 68608 (weights) + 48128 (Cuv)
// =====================================================================
__global__ void __launch_bounds__(256) prep_kernel(
    const float* __restrict__ fc1w, const float* __restrict__ fc2w,
    const float* __restrict__ fc3w, const float* __restrict__ emb,
    const int* __restrict__ edges, const float* __restrict__ w1)
{
    int idx = blockIdx.x * 256 + threadIdx.x;
    if (idx < 3072) {                 // W1: [n=128][kp=24], linear (padded)
        int n = idx / 24, k = idx % 24;
        float val = (k < 16) ? fc1w[k * 128 + n] : 0.0f;
        __nv_bfloat16 hh, ll; bsplit(val, hh, ll);
        g_W1[n * 24 + k] = hh; g_W1[3072 + n * 24 + k] = ll;
    } else if (idx < 35840) {         // W2: pieces [(h*2+c)]: hi 8192 | lo 8192, rowb=128
        int j = idx - 3072;
        int h = j >> 14, c = (j >> 13) & 1;
        int j2 = j & 8191;
        int n = j2 >> 6, k = j2 & 63;
        float val = fc2w[(c * 64 + k) * 256 + h * 128 + n];
        int eo = n * 64 + (((k * 2) ^ ((n & 7) << 4)) >> 1);
        int ph = (h * 2 + c) * 16384 + eo;
        __nv_bfloat16 hh, ll; bsplit(val, hh, ll);
        g_W2[ph] = hh; g_W2[ph + 8192] = ll;
    } else if (idx < 68608) {         // W3: k-halves, [128n][128k] rowb=256 swizzle
        int j = idx - 35840;          // 0..32767
        int n = j >> 8, k = j & 255;
        int kh = k >> 7, kl = k & 127;
        float val = fc3w[k * 128 + n];
        int eo = n * 128 + (((kl * 2) ^ ((n & 7) << 4)) >> 1);
        int ph = kh * 32768 + eo;
        __nv_bfloat16 hh, ll; bsplit(val, hh, ll);
        g_W3[ph] = hh; g_W3[ph + 16384] = ll;
    } else if (idx < 116736) {        // Cuv: conv1 u,v-part per (oi, e)
        int j = idx - 68608;          // 0..48127
        int oi = j >> 8, e = j & 255;
        int o = oi / 47, pos = oi - o * 47;
        int u = edges[2 * e], v = edges[2 * e + 1];
        const float* xu = emb + u * D_EMB + 2 * pos;
        const float* xv = emb + v * D_EMB + 2 * pos;
        const float* wu = w1 + (o * 4 + 2) * 3;
        const float* wv = w1 + (o * 4 + 3) * 3;
        g_Cuv[oi * 256 + e] =
              wu[0] * xu[0] + wu[1] * xu[1] + wu[2] * xu[2]
            + wv[0] * xv[0] + wv[1] * xv[1] + wv[2] * xv[2];
    }
}

// =====================================================================
// Kernel 1: conv stack. conv1 = Rst(s,t per CTA) + Cuv(e, precomputed).
// No semb, no per-thread conv1 FMA. Skips s==t blocks.
// =====================================================================
__global__ void __launch_bounds__(256) conv_kernel(
    const float* __restrict__ emb,
    const float* __restrict__ w1, const float* __restrict__ b1,
    const float* __restrict__ w2, const float* __restrict__ b2,
    const float* __restrict__ w3, const float* __restrict__ b3)
{
    int p = blockIdx.x;
    int s = p >> 5, t = p & 31;
    if (s == t) return;               // fc skips these tiles; output unused

    __shared__ float sw2[48], sw3[48];
    __shared__ float sb2[4], sb3[4];
    __shared__ float Rst[188];        // [o*47 + pos]: bias + s-chan + t-chan
    int tid = threadIdx.x;
    if (tid < 48) { sw2[tid] = w2[tid]; sw3[tid] = w3[tid]; }
    if (tid < 4)  { sb2[tid] = b2[tid]; sb3[tid] = b3[tid]; }

    // build Rst: 188 entries, 6 FMA each (s,t channels of conv1 + bias)
    if (tid < 188) {
        int o = tid / 47, i = tid - o * 47;
        const float* xs_ = emb + s * D_EMB + 2 * i;
        const float* xt_ = emb + t * D_EMB + 2 * i;
        const float* ws_ = w1 + (o * 4 + 0) * 3;
        const float* wt_ = w1 + (o * 4 + 1) * 3;
        Rst[tid] = b1[o]
                 + ws_[0] * xs_[0] + ws_[1] * xs_[1] + ws_[2] * xs_[2]
                 + wt_[0] * xt_[0] + wt_[1] * xt_[1] + wt_[2] * xt_[2];
    }
    __syncthreads();

    int m = p * 256 + tid;
    int e = tid;

    // conv1 = Rst + Cuv (coalesced LDG), relu + pool2 -> p1[4][23]
    float p1[4][23];
    #pragma unroll
    for (int o = 0; o < 4; o++) {
        #pragma unroll
        for (int i = 0; i < 23; i++) {
            int oi = o * 47 + 2 * i;
            float c0 = g_Cuv[oi * 256 + e]        + Rst[oi];
            float c1 = g_Cuv[(oi + 1) * 256 + e]  + Rst[oi + 1];
            p1[o][i] = fmaxf(fmaxf(c0, c1), 0.0f);   // relu(max) == max(relu)
        }
    }

    // conv2 (stride 1, 23->21) + relu + pool2 -> 10
    float p2[4][10];
    #pragma unroll
    for (int i = 0; i < 10; i++) {
        #pragma unroll
        for (int o = 0; o < 4; o++) {
            float a0 = sb2[o], a1 = sb2[o];
            #pragma unroll
            for (int c = 0; c < 4; c++)
                #pragma unroll
                for (int k = 0; k < 3; k++) {
                    float wv = sw2[(o * 4 + c) * 3 + k];
                    a0 = fmaf(wv, p1[c][2 * i + k],     a0);
                    a1 = fmaf(wv, p1[c][2 * i + 1 + k], a1);
                }
            p2[o][i] = fmaxf(fmaxf(a0, a1), 0.0f);
        }
    }
    // conv3 (10->8) + relu + pool2 -> 4; flatten [o*4 + pos]
    #pragma unroll
    for (int pos = 0; pos < 4; pos++) {
        #pragma unroll
        for (int o = 0; o < 4; o++) {
            float a0 = sb3[o], a1 = sb3[o];
            #pragma unroll
            for (int c = 0; c < 4; c++)
                #pragma unroll
                for (int k = 0; k < 3; k++) {
                    float wv = sw3[(o * 4 + c) * 3 + k];
                    a0 = fmaf(wv, p2[c][2 * pos + k],     a0);
                    a1 = fmaf(wv, p2[c][2 * pos + 1 + k], a1);
                }
            g_G[(o * 4 + pos) * M_TOT + m] = fmaxf(fmaxf(a0, a1), 0.0f);
        }
    }
}

// =====================================================================
// Kernel 2: fused FC chain on HMMA, cp.async double-buffered staging.
// =====================================================================
#define OFF_A2  0
#define OFF_A3  65536
#define OFF_WST 196608
#define FC_SMEM 229376

__device__ __forceinline__ void zero_acc(float acc[2][8][4]) {
    #pragma unroll
    for (int i = 0; i < 2; i++)
        #pragma unroll
        for (int j = 0; j < 8; j++)
            #pragma unroll
            for (int q = 0; q < 4; q++) acc[i][j][q] = 0.f;
}
__device__ __forceinline__ void mma_tile(float acc[2][8][4],
                                         uint32_t a[2][4], uint32_t b[4][4]) {
    #pragma unroll
    for (int i = 0; i < 2; i++)
        #pragma unroll
        for (int p = 0; p < 4; p++) {
            mma16816(acc[i][2 * p],     a[i], b[p][0], b[p][1]);
            mma16816(acc[i][2 * p + 1], a[i], b[p][2], b[p][3]);
        }
}
__device__ __forceinline__ void load_afrag(uint32_t base, int mb, int kb0, int rowb,
                                           int mi, int r8, uint32_t a[2][4]) {
    #pragma unroll
    for (int i = 0; i < 2; i++) {
        int m = mb + i * 16 + r8 + ((mi & 1) << 3);
        int kb = kb0 + ((mi >> 1) << 4);
        ldsm4(base + swz(m, kb, rowb), a[i]);
    }
}
__device__ __forceinline__ void load_bfrag(uint32_t base, int nb, int kb0, int rowb,
                                           int mi, int r8, uint32_t b[4][4]) {
    #pragma unroll
    for (int p = 0; p < 4; p++) {
        int n = nb + p * 16 + r8 + ((mi >> 1) << 3);
        int kb = kb0 + ((mi & 1) << 4);
        ldsm4(base + swz(n, kb, rowb), b[p]);
    }
}
__device__ __forceinline__ void store_pair(uint32_t hib, uint32_t lob, int m, int col,
                                           int rowb, float v0, float v1) {
    __nv_bfloat16 h0, l0, h1, l1;
    bsplit(v0, h0, l0); bsplit(v1, h1, l1);
    uint32_t off = swz(m, col * 2, rowb);
    sts32(hib + off, pk(h0, h1));
    sts32(lob + off, pk(l0, l1));
}
__device__ __forceinline__ void epilogue_act(float acc[2][8][4],
    uint32_t hib, uint32_t lob, int rowb, int mb, int nb, int kofs,
    const float* __restrict__ bias, int r4, int c4)
{
    #pragma unroll
    for (int i = 0; i < 2; i++)
        #pragma unroll
        for (int j = 0; j < 8; j++) {
            int col = nb + j * 8 + c4 * 2;
            int dc = kofs + col;
            float b0 = __ldg(bias + dc), b1 = __ldg(bias + dc + 1);
            int m = mb + i * 16 + r4;
            store_pair(hib, lob, m, dc, rowb,
                       fmaxf(acc[i][j][0] + b0, 0.f), fmaxf(acc[i][j][1] + b1, 0.f));
            store_pair(hib, lob, m + 8, dc, rowb,
                       fmaxf(acc[i][j][2] + b0, 0.f), fmaxf(acc[i][j][3] + b1, 0.f));
        }
}

__global__ void __launch_bounds__(256) fc_kernel(
    const float* __restrict__ fc1b, const float* __restrict__ fc2b,
    const float* __restrict__ fc3b, const float* __restrict__ fc4w,
    const float* __restrict__ fc4b)
{
    const int m0 = blockIdx.x * 128;
    const int pp = m0 >> 8;
    if ((pp >> 5) == (pp & 31)) return;   // masked tile: prop writes zeros itself

    extern __shared__ char sm[];
    const uint32_t smb = smem_u32(sm);
    const int tid = threadIdx.x;
    const int l = tid & 31, w = tid >> 5;
    const int wm = w & 3, wn = w >> 2;
    const int mb = wm * 32, nb = wn * 64;
    const int mi = l >> 3, r8 = l & 7;
    const int r4 = l >> 2, c4 = l & 3;

    const uint32_t A1h = smb + OFF_A3, A1l = A1h + 6144;
    const uint32_t W1h = A1h + 12288, W1l = A1h + 18432;
    const uint32_t A2h = smb + OFF_A2, A2l = A2h + 32768;
    const uint32_t A3h = smb + OFF_A3, A3l = A3h + 65536;
    const uint32_t WST = smb + OFF_WST;

    // pre-issue fc2 piece 0 into WST buf0 (hidden under fc1 staging/compute)
    stage16k(WST, g_W2, tid); CP_COMMIT();

    // ---- stage A1 (from g_G, padded kp=24) + W1 ----
    {
        __nv_bfloat16* a1h = (__nv_bfloat16*)(sm + OFF_A3);
        __nv_bfloat16* a1l = (__nv_bfloat16*)(sm + OFF_A3 + 6144);
        for (int idx = tid; idx < 2048; idx += 256) {
            int k = idx >> 7, m = idx & 127;
            float v = g_G[k * M_TOT + m0 + m];
            __nv_bfloat16 h, lo; bsplit(v, h, lo);
            a1h[m * 24 + k] = h; a1l[m * 24 + k] = lo;
        }
        copyg(sm + OFF_A3 + 12288, g_W1, 12288, tid);
    }
    __syncthreads();

    float acc[2][8][4];
    uint32_t ah[2][4], al[2][4], bh[4][4], bl[4][4];

    // ---- fc1: K=16, N=128 -> A2 ----
    zero_acc(acc);
    {
        #pragma unroll
        for (int i = 0; i < 2; i++) {
            int m = mb + i * 16 + r8 + ((mi & 1) << 3);
            int kb = (mi >> 1) << 4;
            ldsm4(A1h + m * 48 + kb, ah[i]);
            ldsm4(A1l + m * 48 + kb, al[i]);
        }
        #pragma unroll
        for (int p = 0; p < 4; p++) {
            int n = nb + p * 16 + r8 + ((mi >> 1) << 3);
            int kb = (mi & 1) << 4;
            ldsm4(W1h + n * 48 + kb, bh[p]);
            ldsm4(W1l + n * 48 + kb, bl[p]);
        }
        mma_tile(acc, ah, bh);
        mma_tile(acc, ah, bl);
        mma_tile(acc, al, bh);
    }
    epilogue_act(acc, A2h, A2l, 256, mb, nb, 0, fc1b, r4, c4);

    // ---- fc2: K=128, N=256. 8 pipelined pieces of 16KB: (h,c)->hi,lo ----
    #pragma unroll 1
    for (int ip = 0; ip < 8; ip++) {
        CP_WAIT0();
        __syncthreads();     // piece ip visible; all warps done with piece ip-1
        if (ip < 7) { stage16k(WST + ((ip + 1) & 1) * 16384, g_W2 + (ip + 1) * 8192, tid); CP_COMMIT(); }
        const int h = ip >> 2, c = (ip >> 1) & 1, term = ip & 1;
        if ((ip & 3) == 0) zero_acc(acc);
        const uint32_t wb = WST + (ip & 1) * 16384;
        #pragma unroll
        for (int ks = 0; ks < 4; ks++) {
            int kbA = (c * 64 + ks * 16) * 2;
            int kbW = ks * 32;
            if (term == 0) {
                load_afrag(A2h, mb, kbA, 256, mi, r8, ah);
                load_afrag(A2l, mb, kbA, 256, mi, r8, al);
                load_bfrag(wb, nb, kbW, 128, mi, r8, bh);
                mma_tile(acc, ah, bh);
                mma_tile(acc, al, bh);
            } else {
                load_afrag(A2h, mb, kbA, 256, mi, r8, ah);
                load_bfrag(wb, nb, kbW, 128, mi, r8, bl);
                mma_tile(acc, ah, bl);
            }
        }
        if (ip == 3) epilogue_act(acc, A3h, A3l, 512, mb, nb, 0,   fc2b, r4, c4);
        if (ip == 7) epilogue_act(acc, A3h, A3l, 512, mb, nb, 128, fc2b, r4, c4);
    }
    __syncthreads();   // all warps done reading A2 + fc2 epilogue written

    // ---- fc3: K=256, N=128. 4 pipelined pieces of 32KB in A2 region ----
    stage32k(smb + OFF_A2, g_W3, tid); CP_COMMIT();
    zero_acc(acc);
    #pragma unroll 1
    for (int ip = 0; ip < 4; ip++) {
        CP_WAIT0();
        __syncthreads();
        if (ip < 3) { stage32k(smb + OFF_A2 + ((ip + 1) & 1) * 32768, g_W3 + (ip + 1) * 16384, tid); CP_COMMIT(); }
        const int kh = ip >> 1, term = ip & 1;
        const uint32_t wb = smb + OFF_A2 + (ip & 1) * 32768;
        #pragma unroll
        for (int ks = 0; ks < 8; ks++) {
            int kbA = (kh * 128 + ks * 16) * 2;
            int kbW = ks * 32;
            if (term == 0) {
                load_afrag(A3h, mb, kbA, 512, mi, r8, ah);
                load_afrag(A3l, mb, kbA, 512, mi, r8, al);
                load_bfrag(wb, nb, kbW, 256, mi, r8, bh);
                mma_tile(acc, ah, bh);
                mma_tile(acc, al, bh);
            } else {
                load_afrag(A3h, mb, kbA, 512, mi, r8, ah);
                load_bfrag(wb, nb, kbW, 256, mi, r8, bl);
                mma_tile(acc, ah, bl);
            }
        }
    }

    // ---- fc4: bias+relu+dot in regs, quad-shfl reduce, smem combine ----
    float part[4] = {0.f, 0.f, 0.f, 0.f};
    #pragma unroll
    for (int i = 0; i < 2; i++)
        #pragma unroll
        for (int j = 0; j < 8; j++) {
            int col = nb + j * 8 + c4 * 2;
            float b0 = __ldg(fc3b + col), b1 = __ldg(fc3b + col + 1);
            float w0 = __ldg(fc4w + col), w1 = __ldg(fc4w + col + 1);
            part[i * 2 + 0] += fmaxf(acc[i][j][0] + b0, 0.f) * w0
                             + fmaxf(acc[i][j][1] + b1, 0.f) * w1;
            part[i * 2 + 1] += fmaxf(acc[i][j][2] + b0, 0.f) * w0
                             + fmaxf(acc[i][j][3] + b1, 0.f) * w1;
        }
    #pragma unroll
    for (int q = 0; q < 4; q++) {
        part[q] += __shfl_xor_sync(0xffffffff, part[q], 1);
        part[q] += __shfl_xor_sync(0xffffffff, part[q], 2);
    }
    float* red = (float*)(sm + OFF_WST);
    __syncthreads();
    if (c4 == 0) {
        #pragma unroll
        for (int i = 0; i < 2; i++) {
            red[wn * 128 + mb + i * 16 + r4]     = part[i * 2];
            red[wn * 128 + mb + i * 16 + r4 + 8] = part[i * 2 + 1];
        }
    }
    __syncthreads();
    if (tid < 128) {
        float v = red[tid] + red[128 + tid] + __ldg(fc4b);
        g_preds[m0 + tid] = v;
    }
}

// =====================================================================
// Kernel 3: 3-step propagation, block per p. Deterministic.
// =====================================================================
__global__ void __launch_bounds__(256) prop_kernel(const int* __restrict__ edges)
{
    __shared__ float xs[32];
    __shared__ float xn[8][32];
    __shared__ float acc[32];
    __shared__ float pr[256];
    __shared__ int   su[256], sv[256];
    int tid = threadIdx.x;
    int p = blockIdx.x;
    int s = p >> 5, t = p & 31;
    su[tid] = edges[2 * tid];
    sv[tid] = edges[2 * tid + 1];
    if (s != t) pr[tid] = g_preds[p * 256 + tid];
    if (tid < 32) { xs[tid] = (tid == s) ? 1.0f : 0.0f; acc[tid] = 0.0f; }
    __syncthreads();
    if (s != t) {
        int j = tid & 31, grp = tid >> 5;
        for (int step = 0; step < 3; step++) {
            float sum = 0.0f;
            #pragma unroll 4
            for (int q = 0; q < 32; q++) {
                int e = grp * 32 + q;
                sum += (sv[e] == j) ? xs[su[e]] * pr[e] : 0.0f;
            }
            xn[grp][j] = sum;
            __syncthreads();
            if (tid < 32) {
                float v = 0.0f;
                #pragma unroll
                for (int g2 = 0; g2 < 8; g2++) v += xn[g2][tid];
                xs[tid] = v;
                acc[tid] += v;
            }
            __syncthreads();
        }
    }
    if (tid < 32) g_part[p * 32 + tid] = acc[tid];
}

// =====================================================================
// Kernel 4: final reduction + normalize.
// =====================================================================
__global__ void __launch_bounds__(1024) reduce_kernel(float* __restrict__ out)
{
    __shared__ float red[32][32];
    __shared__ float rbc[32];
    __shared__ float tot;
    int tid = threadIdx.x;
    int j = tid & 31, chunk = tid >> 5;
    float sum = 0.0f;
    for (int q = 0; q < 32; q++)
        sum += g_part[(chunk * 32 + q) * 32 + j];
    red[chunk][j] = sum;
    __syncthreads();
    if (tid < 32) {
        float v = 0.0f;
        for (int c = 0; c < 32; c++) v += red[c][tid];
        rbc[tid] = v;
    }
    __syncthreads();
    if (tid == 0) {
        float tt = 0.0f;
        for (int k = 0; k < 32; k++) tt += rbc[k];
        tot = tt;
    }
    __syncthreads();
    if (tid < 32) out[tid] = rbc[tid] / tot;
}

// =====================================================================
extern "C" void kernel_launch(void* const* d_in, const int* in_sizes, int n_in,
                              void* d_out, int out_size)
{
    const float* emb   = (const float*)d_in[0];
    const int*   edges = (const int*)  d_in[1];
    const float* w1    = (const float*)d_in[2];
    const float* b1    = (const float*)d_in[3];
    const float* w2    = (const float*)d_in[4];
    const float* b2    = (const float*)d_in[5];
    const float* w3    = (const float*)d_in[6];
    const float* b3    = (const float*)d_in[7];
    const float* fc1w  = (const float*)d_in[8];
    const float* fc1b  = (const float*)d_in[9];
    const float* fc2w  = (const float*)d_in[10];
    const float* fc2b  = (const float*)d_in[11];
    const float* fc3w  = (const float*)d_in[12];
    const float* fc3b  = (const float*)d_in[13];
    const float* fc4w  = (const float*)d_in[14];
    const float* fc4b  = (const float*)d_in[15];

    prep_kernel<<<456, 256>>>(fc1w, fc2w, fc3w, emb, edges, w1);

    conv_kernel<<<P_PAIRS, 256>>>(emb, w1, b1, w2, b2, w3, b3);

    cudaFuncSetAttribute(fc_kernel, cudaFuncAttributeMaxDynamicSharedMemorySize, FC_SMEM);
    fc_kernel<<<M_TOT / 128, 256, FC_SMEM>>>(fc1b, fc2b, fc3b, fc4w, fc4b);

    prop_kernel<<<P_PAIRS, 256>>>(edges);
    reduce_kernel<<<1, 1024>>>((float*)d_out);
}